// round 4
// baseline (speedup 1.0000x reference)
#include <cuda_runtime.h>
#include <cuda_bf16.h>
#include <math.h>

// ---------------- problem constants ----------------
#define BB      2
#define CC0     48          // dim
#define NHEADS  2
#define CHD     24          // channels per head
#define DP      32          // padded head dim (bf16 tensors)
#define NTOK    4096        // 64*64
#define NPIX    (BB*NTOK)   // 8192
#define C3      144         // dim*3
#define HID     96
#define HID2    192
#define NSPL    8           // attention KV splits
#define PSTR    28          // per-split partial record (floats, 16B aligned)

// ---------------- scratch (device globals; no allocation allowed) ----------
__device__ float g_qkv1[BB*C3*NTOK];
__device__ __nv_bfloat16 g_qb[BB*NHEADS*NTOK*DP];
__device__ __nv_bfloat16 g_kb[BB*NHEADS*NTOK*DP];
__device__ __nv_bfloat16 g_vb[BB*NHEADS*NTOK*DP];
__device__ float g_part[BB*NHEADS*NTOK*NSPL*PSTR]; // unnormalized O + l
__device__ float g_o [BB*CC0*NTOK];                // merged attn out, channel-major
__device__ float g_x1[BB*CC0*NTOK];
__device__ float g_ff1[BB*HID2*NTOK];
__device__ float g_ff3[BB*HID*NTOK];               // gated hidden

// ---------------- small asm helpers ----------------------------------------
__device__ __forceinline__ unsigned smem_u32(const void* p) {
    return (unsigned)__cvta_generic_to_shared(p);
}
__device__ __forceinline__ void ldmx4(unsigned& r0, unsigned& r1, unsigned& r2,
                                      unsigned& r3, unsigned a) {
    asm volatile("ldmatrix.sync.aligned.m8n8.x4.shared.b16 {%0,%1,%2,%3}, [%4];"
                 : "=r"(r0), "=r"(r1), "=r"(r2), "=r"(r3) : "r"(a));
}
__device__ __forceinline__ void ldmx4t(unsigned& r0, unsigned& r1, unsigned& r2,
                                       unsigned& r3, unsigned a) {
    asm volatile("ldmatrix.sync.aligned.m8n8.x4.trans.shared.b16 {%0,%1,%2,%3}, [%4];"
                 : "=r"(r0), "=r"(r1), "=r"(r2), "=r"(r3) : "r"(a));
}
__device__ __forceinline__ void mma16816(float& d0, float& d1, float& d2, float& d3,
                                         unsigned a0, unsigned a1, unsigned a2, unsigned a3,
                                         unsigned b0, unsigned b1) {
    asm volatile("mma.sync.aligned.m16n8k16.row.col.f32.bf16.bf16.f32 "
                 "{%0,%1,%2,%3},{%4,%5,%6,%7},{%8,%9},{%0,%1,%2,%3};"
                 : "+f"(d0), "+f"(d1), "+f"(d2), "+f"(d3)
                 : "r"(a0), "r"(a1), "r"(a2), "r"(a3), "r"(b0), "r"(b1));
}
__device__ __forceinline__ unsigned cvt2(float hi, float lo) {
    unsigned r;
    asm("cvt.rn.bf16x2.f32 %0, %1, %2;" : "=r"(r) : "f"(hi), "f"(lo));
    return r;
}
__device__ __forceinline__ float ex2f(float x) {
    float y; asm("ex2.approx.ftz.f32 %0, %1;" : "=f"(y) : "f"(x)); return y;
}

// ---------------- 1x1 conv (optionally LN in, residual out), z-sliced ------
template<int CIN, int COUT, int OPT, bool LN>
__global__ void __launch_bounds__(256)
conv1x1_z(const float* __restrict__ in,
          const float* __restrict__ lnw, const float* __restrict__ lnb,
          const float* __restrict__ w,   const float* __restrict__ bias,
          const float* __restrict__ res, float* __restrict__ out)
{
    __shared__ float ws[CIN*OPT];      // [c][oo]
    const int o0 = blockIdx.y * OPT;
    for (int i = threadIdx.x; i < CIN*OPT; i += 256) {
        int oo = i % OPT, c = i / OPT;
        ws[i] = w[(o0 + oo)*CIN + c];
    }
    __syncthreads();

    int pix = blockIdx.x*256 + threadIdx.x;
    int b = pix >> 12, n = pix & (NTOK-1);
    const float* ip = in + (size_t)b*CIN*NTOK + n;

    float acc[OPT];
    #pragma unroll
    for (int oo = 0; oo < OPT; oo++) acc[oo] = bias[o0 + oo];

    if (LN) {
        float v[CIN];
        float s = 0.f, ss = 0.f;
        #pragma unroll
        for (int c = 0; c < CIN; c++) {
            float u = ip[c*NTOK];
            v[c] = u; s += u; ss += u*u;
        }
        float mu  = s * (1.f/CIN);
        float var = ss * (1.f/CIN) - mu*mu;
        float inv = rsqrtf(var + 1e-5f);
        #pragma unroll
        for (int c = 0; c < CIN; c++) {
            float xc = (v[c] - mu)*inv*__ldg(lnw + c) + __ldg(lnb + c);
            #pragma unroll
            for (int oo = 0; oo < OPT; oo++)
                acc[oo] = fmaf(xc, ws[c*OPT + oo], acc[oo]);
        }
    } else {
        #pragma unroll 4
        for (int c = 0; c < CIN; c++) {
            float xc = ip[c*NTOK];
            #pragma unroll
            for (int oo = 0; oo < OPT; oo++)
                acc[oo] = fmaf(xc, ws[c*OPT + oo], acc[oo]);
        }
    }

    float* op = out + (size_t)(b*COUT + o0)*NTOK + n;
    if (res) {
        const float* rp = res + (size_t)(b*COUT + o0)*NTOK + n;
        #pragma unroll
        for (int oo = 0; oo < OPT; oo++) op[oo*NTOK] = acc[oo] + rp[oo*NTOK];
    } else {
        #pragma unroll
        for (int oo = 0; oo < OPT; oo++) op[oo*NTOK] = acc[oo];
    }
}

// ------- fused: depthwise 3x3 over 144ch + split/l2norm/temp + bf16 emit ---
// thread = (b, head, token); computes dwconv for its 72 channels in-register.
__global__ void __launch_bounds__(256)
dwconv_norm_kernel(const float* __restrict__ in, const float* __restrict__ w,
                   const float* __restrict__ bias, const float* __restrict__ temp,
                   __nv_bfloat16* __restrict__ Q, __nv_bfloat16* __restrict__ K,
                   __nv_bfloat16* __restrict__ V)
{
    int idx = blockIdx.x*blockDim.x + threadIdx.x;   // over BB*NHEADS*NTOK
    int n  = idx & (NTOK-1);
    int bh = idx >> 12;
    int b = bh >> 1, hd = bh & 1;
    int x0 = n & 63, y0 = n >> 6;

    // precompute the 9 tap offsets + validity
    int off[9]; bool val[9];
    #pragma unroll
    for (int ky = 0; ky < 3; ky++) {
        int y = y0 + ky - 1;
        #pragma unroll
        for (int kx = 0; kx < 3; kx++) {
            int xx = x0 + kx - 1;
            int t = ky*3 + kx;
            val[t] = ((unsigned)y < 64u) && ((unsigned)xx < 64u);
            off[t] = y*64 + xx;
        }
    }

    float t = temp[hd];
    float buf[CHD];
    unsigned tmp[DP/2];
    #pragma unroll
    for (int i = CHD/2; i < DP/2; i++) tmp[i] = 0u;

    // ---- q ----
    float ss = 0.f;
    #pragma unroll
    for (int c = 0; c < CHD; c++) {
        int ch = hd*CHD + c;
        const float* ip = in + ((size_t)b*C3 + ch)*NTOK;
        const float* wp = w + ch*9;
        float acc = bias[ch];
        #pragma unroll
        for (int tt = 0; tt < 9; tt++) if (val[tt]) acc += wp[tt]*ip[off[tt]];
        buf[c] = acc; ss += acc*acc;
    }
    float inv = t / fmaxf(sqrtf(ss), 1e-12f);
    #pragma unroll
    for (int i = 0; i < CHD/2; i++) tmp[i] = cvt2(buf[2*i+1]*inv, buf[2*i]*inv);
    {
        uint4* p4 = (uint4*)(Q + (size_t)idx*DP);
        p4[0] = make_uint4(tmp[0], tmp[1], tmp[2],  tmp[3]);
        p4[1] = make_uint4(tmp[4], tmp[5], tmp[6],  tmp[7]);
        p4[2] = make_uint4(tmp[8], tmp[9], tmp[10], tmp[11]);
        p4[3] = make_uint4(tmp[12],tmp[13],tmp[14], tmp[15]);
    }
    // ---- k ----
    ss = 0.f;
    #pragma unroll
    for (int c = 0; c < CHD; c++) {
        int ch = CC0 + hd*CHD + c;
        const float* ip = in + ((size_t)b*C3 + ch)*NTOK;
        const float* wp = w + ch*9;
        float acc = bias[ch];
        #pragma unroll
        for (int tt = 0; tt < 9; tt++) if (val[tt]) acc += wp[tt]*ip[off[tt]];
        buf[c] = acc; ss += acc*acc;
    }
    inv = 1.f / fmaxf(sqrtf(ss), 1e-12f);
    #pragma unroll
    for (int i = 0; i < CHD/2; i++) tmp[i] = cvt2(buf[2*i+1]*inv, buf[2*i]*inv);
    {
        uint4* p4 = (uint4*)(K + (size_t)idx*DP);
        p4[0] = make_uint4(tmp[0], tmp[1], tmp[2],  tmp[3]);
        p4[1] = make_uint4(tmp[4], tmp[5], tmp[6],  tmp[7]);
        p4[2] = make_uint4(tmp[8], tmp[9], tmp[10], tmp[11]);
        p4[3] = make_uint4(tmp[12],tmp[13],tmp[14], tmp[15]);
    }
    // ---- v ----
    #pragma unroll
    for (int c = 0; c < CHD; c++) {
        int ch = 2*CC0 + hd*CHD + c;
        const float* ip = in + ((size_t)b*C3 + ch)*NTOK;
        const float* wp = w + ch*9;
        float acc = bias[ch];
        #pragma unroll
        for (int tt = 0; tt < 9; tt++) if (val[tt]) acc += wp[tt]*ip[off[tt]];
        buf[c] = acc;
    }
    #pragma unroll
    for (int i = 0; i < CHD/2; i++) tmp[i] = cvt2(buf[2*i+1], buf[2*i]);
    {
        uint4* p4 = (uint4*)(V + (size_t)idx*DP);
        p4[0] = make_uint4(tmp[0], tmp[1], tmp[2],  tmp[3]);
        p4[1] = make_uint4(tmp[4], tmp[5], tmp[6],  tmp[7]);
        p4[2] = make_uint4(tmp[8], tmp[9], tmp[10], tmp[11]);
        p4[3] = make_uint4(tmp[12],tmp[13],tmp[14], tmp[15]);
    }
}

// ---------------- FFN depthwise 3x3 + gelu gate fused ----------------------
__global__ void dwconv_gate_kernel(const float* __restrict__ in, const float* __restrict__ w,
                                   const float* __restrict__ bias, float* __restrict__ out)
{
    int idx = blockIdx.x*blockDim.x + threadIdx.x;   // over BB*HID*NTOK
    if (idx >= BB*HID*NTOK) return;
    int p  = idx & (NTOK-1);
    int bj = idx >> 12;
    int j  = bj % HID;
    int b  = bj / HID;
    int x0 = p & 63, y0 = p >> 6;
    const float* ip1 = in + ((size_t)b*HID2 + j)*NTOK;
    const float* ip2 = in + ((size_t)b*HID2 + HID + j)*NTOK;
    const float* w1 = w + j*9;
    const float* w2 = w + (HID + j)*9;
    float a  = bias[j];
    float g2 = bias[HID + j];
    #pragma unroll
    for (int ky = 0; ky < 3; ky++) {
        int y = y0 + ky - 1;
        if ((unsigned)y < 64u) {
            #pragma unroll
            for (int kx = 0; kx < 3; kx++) {
                int xx = x0 + kx - 1;
                if ((unsigned)xx < 64u) {
                    a  += w1[ky*3 + kx] * ip1[y*64 + xx];
                    g2 += w2[ky*3 + kx] * ip2[y*64 + xx];
                }
            }
        }
    }
    float g = 0.5f*a*(1.f + erff(a*0.70710678118654752f));
    out[((size_t)b*HID + j)*NTOK + p] = g*g2;
}

// ---------------- bf16 mma.sync flash attention, split-KV -------------------
#define KVSEG (NTOK/NSPL)   // 512

__global__ void __launch_bounds__(256)
attn_mma_kernel(const __nv_bfloat16* __restrict__ Qb,
                const __nv_bfloat16* __restrict__ Kb,
                const __nv_bfloat16* __restrict__ Vb,
                const float* __restrict__ temp,
                float* __restrict__ part)
{
    __shared__ __align__(16) unsigned char smem_raw[2*16384];

    int tid  = threadIdx.x;
    int warp = tid >> 5, lane = tid & 31;
    int g    = lane >> 2;
    int t4   = lane & 3;
    int bh   = blockIdx.y;
    int q0   = blockIdx.x * 128;
    int spl  = blockIdx.z;
    int kv0  = spl * KVSEG;

    const float L2E = 1.4426950408889634f;
    float m  = fabsf(temp[bh & 1]);
    float nm = -m * L2E;

    unsigned qf[8];
    {
        const unsigned* q32 = (const unsigned*)(Qb + (size_t)(bh*NTOK + q0 + warp*16)*DP);
        #pragma unroll
        for (int kt = 0; kt < 2; kt++) {
            qf[kt*4+0] = q32[g*16       + kt*8 + t4];
            qf[kt*4+1] = q32[(g+8)*16   + kt*8 + t4];
            qf[kt*4+2] = q32[g*16       + kt*8 + 4 + t4];
            qf[kt*4+3] = q32[(g+8)*16   + kt*8 + 4 + t4];
        }
    }

    float o[12];
    #pragma unroll
    for (int i = 0; i < 12; i++) o[i] = 0.f;
    float l0 = 0.f, l1 = 0.f;

    const uint4* kg = (const uint4*)(Kb + (size_t)bh*NTOK*DP);
    const uint4* vg = (const uint4*)(Vb + (size_t)bh*NTOK*DP);
    int row = tid >> 2, chk = tid & 3;
    unsigned swz = row*128 + ((chk ^ (row & 7))*16);

    uint4 kreg = kg[(kv0 + row)*4 + chk];
    uint4 vreg = vg[(kv0 + row)*4 + chk];
    int it = 0;

    for (int kb = kv0; kb < kv0 + KVSEG; kb += 64) {
        unsigned char* bufK = smem_raw + it*16384;
        unsigned char* bufV = bufK + 8192;
        *(uint4*)(bufK + swz) = kreg;
        *(uint4*)(bufV + swz) = vreg;
        if (kb + 64 < kv0 + KVSEG) {
            kreg = kg[(kb + 64 + row)*4 + chk];
            vreg = vg[(kb + 64 + row)*4 + chk];
        }
        __syncthreads();

        unsigned pb[16];
        #pragma unroll
        for (int j = 0; j < 8; j++) {
            unsigned b0, b1, b2, b3;
            {
                int r = j*8 + (lane & 7);
                int c = lane >> 3;
                unsigned a = smem_u32(bufK + r*128 + ((c ^ (r & 7))*16));
                ldmx4(b0, b1, b2, b3, a);
            }
            float c0 = 0.f, c1 = 0.f, c2 = 0.f, c3 = 0.f;
            mma16816(c0, c1, c2, c3, qf[0], qf[1], qf[2], qf[3], b0, b1);
            mma16816(c0, c1, c2, c3, qf[4], qf[5], qf[6], qf[7], b2, b3);
            float p0 = ex2f(fmaf(c0, L2E, nm));
            float p1 = ex2f(fmaf(c1, L2E, nm));
            float p2 = ex2f(fmaf(c2, L2E, nm));
            float p3 = ex2f(fmaf(c3, L2E, nm));
            l0 += p0 + p1;
            l1 += p2 + p3;
            pb[(j>>1)*4 + (j&1)*2 + 0] = cvt2(p1, p0);
            pb[(j>>1)*4 + (j&1)*2 + 1] = cvt2(p3, p2);
        }

        #pragma unroll
        for (int t = 0; t < 4; t++) {
            #pragma unroll
            for (int p = 0; p < 2; p++) {
                unsigned b0, b1, b2, b3;
                {
                    int key = t*16 + ((lane >> 3) & 1)*8 + (lane & 7);
                    int c   = p*2 + (lane >> 4);
                    unsigned a = smem_u32(bufV + key*128 + ((c ^ (key & 7))*16));
                    ldmx4t(b0, b1, b2, b3, a);
                }
                int nn = p*2;
                mma16816(o[nn*4+0], o[nn*4+1], o[nn*4+2], o[nn*4+3],
                         pb[t*4], pb[t*4+1], pb[t*4+2], pb[t*4+3], b0, b1);
                if (nn + 1 < 3)
                    mma16816(o[nn*4+4], o[nn*4+5], o[nn*4+6], o[nn*4+7],
                             pb[t*4], pb[t*4+1], pb[t*4+2], pb[t*4+3], b2, b3);
            }
        }
        it ^= 1;
        __syncthreads();
    }

    l0 += __shfl_xor_sync(0xffffffffu, l0, 1);
    l0 += __shfl_xor_sync(0xffffffffu, l0, 2);
    l1 += __shfl_xor_sync(0xffffffffu, l1, 1);
    l1 += __shfl_xor_sync(0xffffffffu, l1, 2);
    size_t r0 = (size_t)(bh*NTOK + q0 + warp*16 + g);
    float* p0 = part + (r0*NSPL + spl)*PSTR;
    float* p1 = part + ((r0 + 8)*NSPL + spl)*PSTR;
    #pragma unroll
    for (int nn = 0; nn < 3; nn++) {
        int cc = nn*8 + t4*2;
        p0[cc]     = o[nn*4+0];
        p0[cc + 1] = o[nn*4+1];
        p1[cc]     = o[nn*4+2];
        p1[cc + 1] = o[nn*4+3];
    }
    if (t4 == 0) { p0[24] = l0; p1[24] = l1; }
}

// ---------------- merge split-KV partials -> channel-major O ---------------
__global__ void attn_merge_kernel(const float* __restrict__ part, float* __restrict__ O)
{
    int idx = blockIdx.x*blockDim.x + threadIdx.x;   // over BB*NHEADS*NTOK
    if (idx >= BB*NHEADS*NTOK) return;
    int n  = idx & (NTOK-1);
    int bh = idx >> 12;
    int b = bh >> 1, hd = bh & 1;
    const float4* pf = (const float4*)(part + (size_t)idx*NSPL*PSTR);
    float oo[CHD];
    #pragma unroll
    for (int c = 0; c < CHD; c++) oo[c] = 0.f;
    float L = 0.f;
    #pragma unroll
    for (int sp = 0; sp < NSPL; sp++) {
        float4 q0 = pf[sp*7 + 0], q1 = pf[sp*7 + 1], q2 = pf[sp*7 + 2];
        float4 q3 = pf[sp*7 + 3], q4 = pf[sp*7 + 4], q5 = pf[sp*7 + 5];
        float4 q6 = pf[sp*7 + 6];
        oo[0]+=q0.x; oo[1]+=q0.y; oo[2]+=q0.z; oo[3]+=q0.w;
        oo[4]+=q1.x; oo[5]+=q1.y; oo[6]+=q1.z; oo[7]+=q1.w;
        oo[8]+=q2.x; oo[9]+=q2.y; oo[10]+=q2.z; oo[11]+=q2.w;
        oo[12]+=q3.x; oo[13]+=q3.y; oo[14]+=q3.z; oo[15]+=q3.w;
        oo[16]+=q4.x; oo[17]+=q4.y; oo[18]+=q4.z; oo[19]+=q4.w;
        oo[20]+=q5.x; oo[21]+=q5.y; oo[22]+=q5.z; oo[23]+=q5.w;
        L += q6.x;
    }
    float invL = 1.f / L;
    float* op = O + ((size_t)b*CC0 + hd*CHD)*NTOK + n;
    #pragma unroll
    for (int c = 0; c < CHD; c++) op[c*NTOK] = oo[c]*invL;
}

// ---------------- launch ----------------------------------------------------
extern "C" void kernel_launch(void* const* d_in, const int* in_sizes, int n_in,
                              void* d_out, int out_size)
{
    const float* x    = (const float*)d_in[0];
    const float* n1w  = (const float*)d_in[1];
    const float* n1b  = (const float*)d_in[2];
    const float* qkvw = (const float*)d_in[3];
    const float* qkvb = (const float*)d_in[4];
    const float* qdww = (const float*)d_in[5];
    const float* qdwb = (const float*)d_in[6];
    const float* temp = (const float*)d_in[7];
    const float* pw   = (const float*)d_in[8];
    const float* pb   = (const float*)d_in[9];
    const float* n2w  = (const float*)d_in[10];
    const float* n2b  = (const float*)d_in[11];
    const float* fiw  = (const float*)d_in[12];
    const float* fib  = (const float*)d_in[13];
    const float* fdww = (const float*)d_in[14];
    const float* fdwb = (const float*)d_in[15];
    const float* fow  = (const float*)d_in[16];
    const float* fob  = (const float*)d_in[17];
    float* out = (float*)d_out;

    float *qkv1, *partp, *Oc, *x1, *ff1, *ff3;
    __nv_bfloat16 *Qp, *Kp, *Vp;
    cudaGetSymbolAddress((void**)&qkv1,  g_qkv1);
    cudaGetSymbolAddress((void**)&Qp,    g_qb);
    cudaGetSymbolAddress((void**)&Kp,    g_kb);
    cudaGetSymbolAddress((void**)&Vp,    g_vb);
    cudaGetSymbolAddress((void**)&partp, g_part);
    cudaGetSymbolAddress((void**)&Oc,    g_o);
    cudaGetSymbolAddress((void**)&x1,    g_x1);
    cudaGetSymbolAddress((void**)&ff1,   g_ff1);
    cudaGetSymbolAddress((void**)&ff3,   g_ff3);

    // 1. LN1 + qkv 1x1 : x -> g_qkv1 [b][144][pix]
    conv1x1_z<CC0, C3, 24, true><<<dim3(NPIX/256, C3/24), 256>>>(
        x, n1w, n1b, qkvw, qkvb, nullptr, qkv1);
    // 2. fused depthwise 3x3 + split/l2norm/bf16
    dwconv_norm_kernel<<<(BB*NHEADS*NTOK)/256, 256>>>(qkv1, qdww, qdwb, temp, Qp, Kp, Vp);
    // 3. flash attention, split-KV
    dim3 ag(NTOK/128, BB*NHEADS, NSPL);
    attn_mma_kernel<<<ag, 256>>>(Qp, Kp, Vp, temp, partp);
    // 4. merge partials -> g_o [b][48][pix]
    attn_merge_kernel<<<(BB*NHEADS*NTOK + 255)/256, 256>>>(partp, Oc);
    // 5. proj 1x1 + residual -> g_x1
    conv1x1_z<CC0, CC0, 12, false><<<dim3(NPIX/256, CC0/12), 256>>>(
        Oc, nullptr, nullptr, pw, pb, x, x1);
    // 6. LN2 + fi 1x1 -> g_ff1 [b][192][pix]
    conv1x1_z<CC0, HID2, 24, true><<<dim3(NPIX/256, HID2/24), 256>>>(
        x1, n2w, n2b, fiw, fib, nullptr, ff1);
    // 7. FFN depthwise + gelu gate -> g_ff3 [b][96][pix]
    dwconv_gate_kernel<<<(BB*HID*NTOK + 255)/256, 256>>>(ff1, fdww, fdwb, ff3);
    // 8. fo 1x1 + residual -> out
    conv1x1_z<HID, CC0, 12, false><<<dim3(NPIX/256, CC0/12), 256>>>(
        ff3, nullptr, nullptr, fow, fob, x1, out);
}

// round 5
// speedup vs baseline: 1.1701x; 1.1701x over previous
#include <cuda_runtime.h>
#include <cuda_bf16.h>
#include <math.h>

// ---------------- problem constants ----------------
#define BB      2
#define CC0     48          // dim
#define NHEADS  2
#define CHD     24          // channels per head
#define DP      32          // padded head dim (bf16 tensors)
#define NTOK    4096        // 64*64
#define NPIX    (BB*NTOK)   // 8192
#define C3      144         // dim*3
#define HID     96
#define HID2    192
#define NSPL    8           // attention KV splits
#define PSTR    28          // per-split partial record (floats, 16B aligned)

// ---------------- scratch (device globals; no allocation allowed) ----------
__device__ float g_qkv1[BB*C3*NTOK];
__device__ __nv_bfloat16 g_qb[BB*NHEADS*NTOK*DP];
__device__ __nv_bfloat16 g_kb[BB*NHEADS*NTOK*DP];
__device__ __nv_bfloat16 g_vb[BB*NHEADS*NTOK*DP];
__device__ float g_part[BB*NHEADS*NTOK*NSPL*PSTR]; // unnormalized O + l
__device__ float g_o [BB*CC0*NTOK];                // merged attn out, channel-major
__device__ float g_x1[BB*CC0*NTOK];
__device__ float g_ff1[BB*HID2*NTOK];
__device__ float g_ff3[BB*HID*NTOK];               // gated hidden

// ---------------- small asm helpers ----------------------------------------
__device__ __forceinline__ unsigned smem_u32(const void* p) {
    return (unsigned)__cvta_generic_to_shared(p);
}
__device__ __forceinline__ void ldmx4(unsigned& r0, unsigned& r1, unsigned& r2,
                                      unsigned& r3, unsigned a) {
    asm volatile("ldmatrix.sync.aligned.m8n8.x4.shared.b16 {%0,%1,%2,%3}, [%4];"
                 : "=r"(r0), "=r"(r1), "=r"(r2), "=r"(r3) : "r"(a));
}
__device__ __forceinline__ void ldmx4t(unsigned& r0, unsigned& r1, unsigned& r2,
                                       unsigned& r3, unsigned a) {
    asm volatile("ldmatrix.sync.aligned.m8n8.x4.trans.shared.b16 {%0,%1,%2,%3}, [%4];"
                 : "=r"(r0), "=r"(r1), "=r"(r2), "=r"(r3) : "r"(a));
}
__device__ __forceinline__ void mma16816(float& d0, float& d1, float& d2, float& d3,
                                         unsigned a0, unsigned a1, unsigned a2, unsigned a3,
                                         unsigned b0, unsigned b1) {
    asm volatile("mma.sync.aligned.m16n8k16.row.col.f32.bf16.bf16.f32 "
                 "{%0,%1,%2,%3},{%4,%5,%6,%7},{%8,%9},{%0,%1,%2,%3};"
                 : "+f"(d0), "+f"(d1), "+f"(d2), "+f"(d3)
                 : "r"(a0), "r"(a1), "r"(a2), "r"(a3), "r"(b0), "r"(b1));
}
__device__ __forceinline__ unsigned cvt2(float hi, float lo) {
    unsigned r;
    asm("cvt.rn.bf16x2.f32 %0, %1, %2;" : "=r"(r) : "f"(hi), "f"(lo));
    return r;
}
__device__ __forceinline__ float ex2f(float x) {
    float y; asm("ex2.approx.ftz.f32 %0, %1;" : "=f"(y) : "f"(x)); return y;
}

// ---------------- 1x1 conv (optionally LN in, residual out), z-sliced ------
template<int CIN, int COUT, int OPT, bool LN>
__global__ void __launch_bounds__(256)
conv1x1_z(const float* __restrict__ in,
          const float* __restrict__ lnw, const float* __restrict__ lnb,
          const float* __restrict__ w,   const float* __restrict__ bias,
          const float* __restrict__ res, float* __restrict__ out)
{
    __shared__ float ws[CIN*OPT];      // [c][oo]
    const int o0 = blockIdx.y * OPT;
    for (int i = threadIdx.x; i < CIN*OPT; i += 256) {
        int oo = i % OPT, c = i / OPT;
        ws[i] = w[(o0 + oo)*CIN + c];
    }
    __syncthreads();

    int pix = blockIdx.x*256 + threadIdx.x;
    int b = pix >> 12, n = pix & (NTOK-1);
    const float* ip = in + (size_t)b*CIN*NTOK + n;

    float acc[OPT];
    #pragma unroll
    for (int oo = 0; oo < OPT; oo++) acc[oo] = bias[o0 + oo];

    if (LN) {
        float v[CIN];
        float s = 0.f, ss = 0.f;
        #pragma unroll
        for (int c = 0; c < CIN; c++) {
            float u = ip[c*NTOK];
            v[c] = u; s += u; ss += u*u;
        }
        float mu  = s * (1.f/CIN);
        float var = ss * (1.f/CIN) - mu*mu;
        float inv = rsqrtf(var + 1e-5f);
        #pragma unroll
        for (int c = 0; c < CIN; c++) {
            float xc = (v[c] - mu)*inv*__ldg(lnw + c) + __ldg(lnb + c);
            #pragma unroll
            for (int oo = 0; oo < OPT; oo++)
                acc[oo] = fmaf(xc, ws[c*OPT + oo], acc[oo]);
        }
    } else {
        #pragma unroll 4
        for (int c = 0; c < CIN; c++) {
            float xc = ip[c*NTOK];
            #pragma unroll
            for (int oo = 0; oo < OPT; oo++)
                acc[oo] = fmaf(xc, ws[c*OPT + oo], acc[oo]);
        }
    }

    float* op = out + (size_t)(b*COUT + o0)*NTOK + n;
    if (res) {
        const float* rp = res + (size_t)(b*COUT + o0)*NTOK + n;
        #pragma unroll
        for (int oo = 0; oo < OPT; oo++) op[oo*NTOK] = acc[oo] + rp[oo*NTOK];
    } else {
        #pragma unroll
        for (int oo = 0; oo < OPT; oo++) op[oo*NTOK] = acc[oo];
    }
}

// ------- fused: depthwise 3x3 + split/l2norm/temp + bf16 emit --------------
// thread = (b, head, token); blockIdx.y = type (0=q,1=k,2=v).
// Each thread computes dwconv for its 24 channels in-register.
__global__ void __launch_bounds__(256)
dwconv_norm_kernel(const float* __restrict__ in, const float* __restrict__ w,
                   const float* __restrict__ bias, const float* __restrict__ temp,
                   __nv_bfloat16* __restrict__ Q, __nv_bfloat16* __restrict__ K,
                   __nv_bfloat16* __restrict__ V)
{
    int idx = blockIdx.x*blockDim.x + threadIdx.x;   // over BB*NHEADS*NTOK
    int typ = blockIdx.y;                            // 0=q, 1=k, 2=v
    int n  = idx & (NTOK-1);
    int bh = idx >> 12;
    int b = bh >> 1, hd = bh & 1;
    int x0 = n & 63, y0 = n >> 6;

    int off[9]; bool val[9];
    #pragma unroll
    for (int ky = 0; ky < 3; ky++) {
        int y = y0 + ky - 1;
        #pragma unroll
        for (int kx = 0; kx < 3; kx++) {
            int xx = x0 + kx - 1;
            int t = ky*3 + kx;
            val[t] = ((unsigned)y < 64u) && ((unsigned)xx < 64u);
            off[t] = y*64 + xx;
        }
    }

    float buf[CHD];
    float ss = 0.f;
    int ch0 = typ*CC0 + hd*CHD;
    #pragma unroll
    for (int c = 0; c < CHD; c++) {
        int ch = ch0 + c;
        const float* ip = in + ((size_t)b*C3 + ch)*NTOK;
        const float* wp = w + ch*9;
        float acc = bias[ch];
        #pragma unroll
        for (int tt = 0; tt < 9; tt++) if (val[tt]) acc += wp[tt]*ip[off[tt]];
        buf[c] = acc; ss += acc*acc;
    }
    float inv;
    __nv_bfloat16* dst;
    if (typ == 0)      { inv = temp[hd] / fmaxf(sqrtf(ss), 1e-12f); dst = Q; }
    else if (typ == 1) { inv = 1.f / fmaxf(sqrtf(ss), 1e-12f);      dst = K; }
    else               { inv = 1.f;                                  dst = V; }

    unsigned tmp[DP/2];
    #pragma unroll
    for (int i = CHD/2; i < DP/2; i++) tmp[i] = 0u;
    #pragma unroll
    for (int i = 0; i < CHD/2; i++) tmp[i] = cvt2(buf[2*i+1]*inv, buf[2*i]*inv);
    uint4* p4 = (uint4*)(dst + (size_t)idx*DP);
    p4[0] = make_uint4(tmp[0], tmp[1], tmp[2],  tmp[3]);
    p4[1] = make_uint4(tmp[4], tmp[5], tmp[6],  tmp[7]);
    p4[2] = make_uint4(tmp[8], tmp[9], tmp[10], tmp[11]);
    p4[3] = make_uint4(tmp[12],tmp[13],tmp[14], tmp[15]);
}

// ---------------- FFN depthwise 3x3 + gelu gate fused ----------------------
__global__ void dwconv_gate_kernel(const float* __restrict__ in, const float* __restrict__ w,
                                   const float* __restrict__ bias, float* __restrict__ out)
{
    int idx = blockIdx.x*blockDim.x + threadIdx.x;   // over BB*HID*NTOK
    if (idx >= BB*HID*NTOK) return;
    int p  = idx & (NTOK-1);
    int bj = idx >> 12;
    int j  = bj % HID;
    int b  = bj / HID;
    int x0 = p & 63, y0 = p >> 6;
    const float* ip1 = in + ((size_t)b*HID2 + j)*NTOK;
    const float* ip2 = in + ((size_t)b*HID2 + HID + j)*NTOK;
    const float* w1 = w + j*9;
    const float* w2 = w + (HID + j)*9;
    float a  = bias[j];
    float g2 = bias[HID + j];
    #pragma unroll
    for (int ky = 0; ky < 3; ky++) {
        int y = y0 + ky - 1;
        if ((unsigned)y < 64u) {
            #pragma unroll
            for (int kx = 0; kx < 3; kx++) {
                int xx = x0 + kx - 1;
                if ((unsigned)xx < 64u) {
                    a  += w1[ky*3 + kx] * ip1[y*64 + xx];
                    g2 += w2[ky*3 + kx] * ip2[y*64 + xx];
                }
            }
        }
    }
    float g = 0.5f*a*(1.f + erff(a*0.70710678118654752f));
    out[((size_t)b*HID + j)*NTOK + p] = g*g2;
}

// ---------------- bf16 mma.sync flash attention, split-KV -------------------
#define KVSEG (NTOK/NSPL)   // 512

__global__ void __launch_bounds__(256)
attn_mma_kernel(const __nv_bfloat16* __restrict__ Qb,
                const __nv_bfloat16* __restrict__ Kb,
                const __nv_bfloat16* __restrict__ Vb,
                const float* __restrict__ temp,
                float* __restrict__ part)
{
    __shared__ __align__(16) unsigned char smem_raw[2*16384];

    int tid  = threadIdx.x;
    int warp = tid >> 5, lane = tid & 31;
    int g    = lane >> 2;
    int t4   = lane & 3;
    int bh   = blockIdx.y;
    int q0   = blockIdx.x * 128;
    int spl  = blockIdx.z;
    int kv0  = spl * KVSEG;

    const float L2E = 1.4426950408889634f;
    float m  = fabsf(temp[bh & 1]);
    float nm = -m * L2E;

    unsigned qf[8];
    {
        const unsigned* q32 = (const unsigned*)(Qb + (size_t)(bh*NTOK + q0 + warp*16)*DP);
        #pragma unroll
        for (int kt = 0; kt < 2; kt++) {
            qf[kt*4+0] = q32[g*16       + kt*8 + t4];
            qf[kt*4+1] = q32[(g+8)*16   + kt*8 + t4];
            qf[kt*4+2] = q32[g*16       + kt*8 + 4 + t4];
            qf[kt*4+3] = q32[(g+8)*16   + kt*8 + 4 + t4];
        }
    }

    float o[12];
    #pragma unroll
    for (int i = 0; i < 12; i++) o[i] = 0.f;
    float l0 = 0.f, l1 = 0.f;

    const uint4* kg = (const uint4*)(Kb + (size_t)bh*NTOK*DP);
    const uint4* vg = (const uint4*)(Vb + (size_t)bh*NTOK*DP);
    int row = tid >> 2, chk = tid & 3;
    unsigned swz = row*128 + ((chk ^ (row & 7))*16);

    uint4 kreg = kg[(kv0 + row)*4 + chk];
    uint4 vreg = vg[(kv0 + row)*4 + chk];
    int it = 0;

    for (int kb = kv0; kb < kv0 + KVSEG; kb += 64) {
        unsigned char* bufK = smem_raw + it*16384;
        unsigned char* bufV = bufK + 8192;
        *(uint4*)(bufK + swz) = kreg;
        *(uint4*)(bufV + swz) = vreg;
        if (kb + 64 < kv0 + KVSEG) {
            kreg = kg[(kb + 64 + row)*4 + chk];
            vreg = vg[(kb + 64 + row)*4 + chk];
        }
        __syncthreads();

        unsigned pb[16];
        #pragma unroll
        for (int j = 0; j < 8; j++) {
            unsigned b0, b1, b2, b3;
            {
                int r = j*8 + (lane & 7);
                int c = lane >> 3;
                unsigned a = smem_u32(bufK + r*128 + ((c ^ (r & 7))*16));
                ldmx4(b0, b1, b2, b3, a);
            }
            float c0 = 0.f, c1 = 0.f, c2 = 0.f, c3 = 0.f;
            mma16816(c0, c1, c2, c3, qf[0], qf[1], qf[2], qf[3], b0, b1);
            mma16816(c0, c1, c2, c3, qf[4], qf[5], qf[6], qf[7], b2, b3);
            float p0 = ex2f(fmaf(c0, L2E, nm));
            float p1 = ex2f(fmaf(c1, L2E, nm));
            float p2 = ex2f(fmaf(c2, L2E, nm));
            float p3 = ex2f(fmaf(c3, L2E, nm));
            l0 += p0 + p1;
            l1 += p2 + p3;
            pb[(j>>1)*4 + (j&1)*2 + 0] = cvt2(p1, p0);
            pb[(j>>1)*4 + (j&1)*2 + 1] = cvt2(p3, p2);
        }

        #pragma unroll
        for (int t = 0; t < 4; t++) {
            #pragma unroll
            for (int p = 0; p < 2; p++) {
                unsigned b0, b1, b2, b3;
                {
                    int key = t*16 + ((lane >> 3) & 1)*8 + (lane & 7);
                    int c   = p*2 + (lane >> 4);
                    unsigned a = smem_u32(bufV + key*128 + ((c ^ (key & 7))*16));
                    ldmx4t(b0, b1, b2, b3, a);
                }
                int nn = p*2;
                mma16816(o[nn*4+0], o[nn*4+1], o[nn*4+2], o[nn*4+3],
                         pb[t*4], pb[t*4+1], pb[t*4+2], pb[t*4+3], b0, b1);
                if (nn + 1 < 3)
                    mma16816(o[nn*4+4], o[nn*4+5], o[nn*4+6], o[nn*4+7],
                             pb[t*4], pb[t*4+1], pb[t*4+2], pb[t*4+3], b2, b3);
            }
        }
        it ^= 1;
        // single sync per iteration is sufficient: next store targets the
        // other buffer; the sync at the top of the next iteration orders the
        // buffer reuse two iterations out.
    }

    l0 += __shfl_xor_sync(0xffffffffu, l0, 1);
    l0 += __shfl_xor_sync(0xffffffffu, l0, 2);
    l1 += __shfl_xor_sync(0xffffffffu, l1, 1);
    l1 += __shfl_xor_sync(0xffffffffu, l1, 2);
    size_t r0 = (size_t)(bh*NTOK + q0 + warp*16 + g);
    float* p0 = part + (r0*NSPL + spl)*PSTR;
    float* p1 = part + ((r0 + 8)*NSPL + spl)*PSTR;
    #pragma unroll
    for (int nn = 0; nn < 3; nn++) {
        int cc = nn*8 + t4*2;
        p0[cc]     = o[nn*4+0];
        p0[cc + 1] = o[nn*4+1];
        p1[cc]     = o[nn*4+2];
        p1[cc + 1] = o[nn*4+3];
    }
    if (t4 == 0) { p0[24] = l0; p1[24] = l1; }
}

// ---------------- merge split-KV partials -> channel-major O ---------------
// 8 lanes per token (lane = split). Contiguous 112B read per lane, butterfly
// reduce over 3 levels, each lane writes 3 channels.
__global__ void __launch_bounds__(256)
attn_merge_kernel(const float* __restrict__ part, float* __restrict__ O)
{
    int gt   = blockIdx.x*256 + threadIdx.x;   // over BB*NHEADS*NTOK*8
    int sp   = gt & 7;
    int idx  = gt >> 3;                        // token id
    int n  = idx & (NTOK-1);
    int bh = idx >> 12;
    int b = bh >> 1, hd = bh & 1;

    const float4* pf = (const float4*)(part + ((size_t)idx*NSPL + sp)*PSTR);
    float v[25];
    #pragma unroll
    for (int i = 0; i < 6; i++) {
        float4 q = pf[i];
        v[i*4+0] = q.x; v[i*4+1] = q.y; v[i*4+2] = q.z; v[i*4+3] = q.w;
    }
    v[24] = pf[6].x;

    #pragma unroll
    for (int off = 1; off < 8; off <<= 1) {
        #pragma unroll
        for (int i = 0; i < 25; i++)
            v[i] += __shfl_xor_sync(0xffffffffu, v[i], off);
    }
    float invL = 1.f / v[24];
    float* op = O + ((size_t)b*CC0 + hd*CHD)*NTOK + n;
    #pragma unroll
    for (int c = 0; c < 3; c++)
        op[(sp*3 + c)*NTOK] = v[sp*3 + c] * invL;
}

// ---------------- launch ----------------------------------------------------
extern "C" void kernel_launch(void* const* d_in, const int* in_sizes, int n_in,
                              void* d_out, int out_size)
{
    const float* x    = (const float*)d_in[0];
    const float* n1w  = (const float*)d_in[1];
    const float* n1b  = (const float*)d_in[2];
    const float* qkvw = (const float*)d_in[3];
    const float* qkvb = (const float*)d_in[4];
    const float* qdww = (const float*)d_in[5];
    const float* qdwb = (const float*)d_in[6];
    const float* temp = (const float*)d_in[7];
    const float* pw   = (const float*)d_in[8];
    const float* pb   = (const float*)d_in[9];
    const float* n2w  = (const float*)d_in[10];
    const float* n2b  = (const float*)d_in[11];
    const float* fiw  = (const float*)d_in[12];
    const float* fib  = (const float*)d_in[13];
    const float* fdww = (const float*)d_in[14];
    const float* fdwb = (const float*)d_in[15];
    const float* fow  = (const float*)d_in[16];
    const float* fob  = (const float*)d_in[17];
    float* out = (float*)d_out;

    float *qkv1, *partp, *Oc, *x1, *ff1, *ff3;
    __nv_bfloat16 *Qp, *Kp, *Vp;
    cudaGetSymbolAddress((void**)&qkv1,  g_qkv1);
    cudaGetSymbolAddress((void**)&Qp,    g_qb);
    cudaGetSymbolAddress((void**)&Kp,    g_kb);
    cudaGetSymbolAddress((void**)&Vp,    g_vb);
    cudaGetSymbolAddress((void**)&partp, g_part);
    cudaGetSymbolAddress((void**)&Oc,    g_o);
    cudaGetSymbolAddress((void**)&x1,    g_x1);
    cudaGetSymbolAddress((void**)&ff1,   g_ff1);
    cudaGetSymbolAddress((void**)&ff3,   g_ff3);

    // 1. LN1 + qkv 1x1 : x -> g_qkv1 [b][144][pix]
    conv1x1_z<CC0, C3, 24, true><<<dim3(NPIX/256, C3/24), 256>>>(
        x, n1w, n1b, qkvw, qkvb, nullptr, qkv1);
    // 2. fused depthwise 3x3 + split/l2norm/bf16 (type-parallel)
    dwconv_norm_kernel<<<dim3((BB*NHEADS*NTOK)/256, 3), 256>>>(
        qkv1, qdww, qdwb, temp, Qp, Kp, Vp);
    // 3. flash attention, split-KV
    dim3 ag(NTOK/128, BB*NHEADS, NSPL);
    attn_mma_kernel<<<ag, 256>>>(Qp, Kp, Vp, temp, partp);
    // 4. merge partials -> g_o [b][48][pix]
    attn_merge_kernel<<<(BB*NHEADS*NTOK*8)/256, 256>>>(partp, Oc);
    // 5. proj 1x1 + residual -> g_x1
    conv1x1_z<CC0, CC0, 12, false><<<dim3(NPIX/256, CC0/12), 256>>>(
        Oc, nullptr, nullptr, pw, pb, x, x1);
    // 6. LN2 + fi 1x1 -> g_ff1 [b][192][pix]
    conv1x1_z<CC0, HID2, 24, true><<<dim3(NPIX/256, HID2/24), 256>>>(
        x1, n2w, n2b, fiw, fib, nullptr, ff1);
    // 7. FFN depthwise + gelu gate -> g_ff3 [b][96][pix]
    dwconv_gate_kernel<<<(BB*HID*NTOK + 255)/256, 256>>>(ff1, fdww, fdwb, ff3);
    // 8. fo 1x1 + residual -> out
    conv1x1_z<HID, CC0, 12, false><<<dim3(NPIX/256, CC0/12), 256>>>(
        ff3, nullptr, nullptr, fow, fob, x1, out);
}

// round 6
// speedup vs baseline: 1.2487x; 1.0671x over previous
#include <cuda_runtime.h>
#include <cuda_bf16.h>
#include <math.h>

// ---------------- problem constants ----------------
#define BB      2
#define CC0     48          // dim
#define NHEADS  2
#define CHD     24          // channels per head
#define DP      32          // padded head dim (bf16 tensors)
#define NTOK    4096        // 64*64
#define NPIX    (BB*NTOK)   // 8192
#define C3      144         // dim*3
#define HID     96
#define HID2    192
#define NSPL    8           // attention KV splits
#define ASTR    28          // accumulator record (floats, 16B aligned): 24 O + l

// ---------------- scratch (device globals; no allocation allowed) ----------
__device__ float g_qkv1[BB*C3*NTOK];
__device__ __nv_bfloat16 g_qb[BB*NHEADS*NTOK*DP];
__device__ __nv_bfloat16 g_kb[BB*NHEADS*NTOK*DP];
__device__ __nv_bfloat16 g_vb[BB*NHEADS*NTOK*DP];
__device__ float g_acc[BB*NHEADS*NTOK*ASTR];       // atomic O/l accumulator
__device__ float g_x1[BB*CC0*NTOK];
__device__ float g_ff1[BB*HID2*NTOK];
__device__ float g_ff3[BB*HID*NTOK];               // gated hidden

#define ACC_N4 ((BB*NHEADS*NTOK*ASTR)/4)           // float4 count = 114688

// ---------------- small asm helpers ----------------------------------------
__device__ __forceinline__ unsigned smem_u32(const void* p) {
    return (unsigned)__cvta_generic_to_shared(p);
}
__device__ __forceinline__ void ldmx4(unsigned& r0, unsigned& r1, unsigned& r2,
                                      unsigned& r3, unsigned a) {
    asm volatile("ldmatrix.sync.aligned.m8n8.x4.shared.b16 {%0,%1,%2,%3}, [%4];"
                 : "=r"(r0), "=r"(r1), "=r"(r2), "=r"(r3) : "r"(a));
}
__device__ __forceinline__ void ldmx4t(unsigned& r0, unsigned& r1, unsigned& r2,
                                       unsigned& r3, unsigned a) {
    asm volatile("ldmatrix.sync.aligned.m8n8.x4.trans.shared.b16 {%0,%1,%2,%3}, [%4];"
                 : "=r"(r0), "=r"(r1), "=r"(r2), "=r"(r3) : "r"(a));
}
__device__ __forceinline__ void mma16816(float& d0, float& d1, float& d2, float& d3,
                                         unsigned a0, unsigned a1, unsigned a2, unsigned a3,
                                         unsigned b0, unsigned b1) {
    asm volatile("mma.sync.aligned.m16n8k16.row.col.f32.bf16.bf16.f32 "
                 "{%0,%1,%2,%3},{%4,%5,%6,%7},{%8,%9},{%0,%1,%2,%3};"
                 : "+f"(d0), "+f"(d1), "+f"(d2), "+f"(d3)
                 : "r"(a0), "r"(a1), "r"(a2), "r"(a3), "r"(b0), "r"(b1));
}
__device__ __forceinline__ unsigned cvt2(float hi, float lo) {
    unsigned r;
    asm("cvt.rn.bf16x2.f32 %0, %1, %2;" : "=r"(r) : "f"(hi), "f"(lo));
    return r;
}
__device__ __forceinline__ float ex2f(float x) {
    float y; asm("ex2.approx.ftz.f32 %0, %1;" : "=f"(y) : "f"(x)); return y;
}

// ---------------- 1x1 conv (optionally LN in), z-sliced ---------------------
// Also optionally zeroes a scratch buffer (piggyback, no extra launch).
template<int CIN, int COUT, int OPT, bool LN>
__global__ void __launch_bounds__(256)
conv1x1_z(const float* __restrict__ in,
          const float* __restrict__ lnw, const float* __restrict__ lnb,
          const float* __restrict__ w,   const float* __restrict__ bias,
          const float* __restrict__ res, float* __restrict__ out,
          float4* zbuf, int zn4)
{
    if (zbuf) {
        int nth  = gridDim.x*gridDim.y*256;
        int ztid = (blockIdx.y*gridDim.x + blockIdx.x)*256 + threadIdx.x;
        float4 z = make_float4(0.f, 0.f, 0.f, 0.f);
        for (int i = ztid; i < zn4; i += nth) zbuf[i] = z;
    }
    __shared__ float ws[CIN*OPT];      // [c][oo]
    const int o0 = blockIdx.y * OPT;
    for (int i = threadIdx.x; i < CIN*OPT; i += 256) {
        int oo = i % OPT, c = i / OPT;
        ws[i] = w[(o0 + oo)*CIN + c];
    }
    __syncthreads();

    int pix = blockIdx.x*256 + threadIdx.x;
    int b = pix >> 12, n = pix & (NTOK-1);
    const float* ip = in + (size_t)b*CIN*NTOK + n;

    float acc[OPT];
    #pragma unroll
    for (int oo = 0; oo < OPT; oo++) acc[oo] = bias[o0 + oo];

    if (LN) {
        float v[CIN];
        float s = 0.f, ss = 0.f;
        #pragma unroll
        for (int c = 0; c < CIN; c++) {
            float u = ip[c*NTOK];
            v[c] = u; s += u; ss += u*u;
        }
        float mu  = s * (1.f/CIN);
        float var = ss * (1.f/CIN) - mu*mu;
        float inv = rsqrtf(var + 1e-5f);
        #pragma unroll
        for (int c = 0; c < CIN; c++) {
            float xc = (v[c] - mu)*inv*__ldg(lnw + c) + __ldg(lnb + c);
            #pragma unroll
            for (int oo = 0; oo < OPT; oo++)
                acc[oo] = fmaf(xc, ws[c*OPT + oo], acc[oo]);
        }
    } else {
        #pragma unroll 4
        for (int c = 0; c < CIN; c++) {
            float xc = ip[c*NTOK];
            #pragma unroll
            for (int oo = 0; oo < OPT; oo++)
                acc[oo] = fmaf(xc, ws[c*OPT + oo], acc[oo]);
        }
    }

    float* op = out + (size_t)(b*COUT + o0)*NTOK + n;
    if (res) {
        const float* rp = res + (size_t)(b*COUT + o0)*NTOK + n;
        #pragma unroll
        for (int oo = 0; oo < OPT; oo++) op[oo*NTOK] = acc[oo] + rp[oo*NTOK];
    } else {
        #pragma unroll
        for (int oo = 0; oo < OPT; oo++) op[oo*NTOK] = acc[oo];
    }
}

// ------- fused: depthwise 3x3 + split/l2norm/temp + bf16 emit --------------
__global__ void __launch_bounds__(256)
dwconv_norm_kernel(const float* __restrict__ in, const float* __restrict__ w,
                   const float* __restrict__ bias, const float* __restrict__ temp,
                   __nv_bfloat16* __restrict__ Q, __nv_bfloat16* __restrict__ K,
                   __nv_bfloat16* __restrict__ V)
{
    int idx = blockIdx.x*blockDim.x + threadIdx.x;   // over BB*NHEADS*NTOK
    int typ = blockIdx.y;                            // 0=q, 1=k, 2=v
    int n  = idx & (NTOK-1);
    int bh = idx >> 12;
    int b = bh >> 1, hd = bh & 1;
    int x0 = n & 63, y0 = n >> 6;

    int off[9]; bool val[9];
    #pragma unroll
    for (int ky = 0; ky < 3; ky++) {
        int y = y0 + ky - 1;
        #pragma unroll
        for (int kx = 0; kx < 3; kx++) {
            int xx = x0 + kx - 1;
            int t = ky*3 + kx;
            val[t] = ((unsigned)y < 64u) && ((unsigned)xx < 64u);
            off[t] = y*64 + xx;
        }
    }

    float buf[CHD];
    float ss = 0.f;
    int ch0 = typ*CC0 + hd*CHD;
    #pragma unroll
    for (int c = 0; c < CHD; c++) {
        int ch = ch0 + c;
        const float* ip = in + ((size_t)b*C3 + ch)*NTOK;
        const float* wp = w + ch*9;
        float acc = bias[ch];
        #pragma unroll
        for (int tt = 0; tt < 9; tt++) if (val[tt]) acc += wp[tt]*ip[off[tt]];
        buf[c] = acc; ss += acc*acc;
    }
    float inv;
    __nv_bfloat16* dst;
    if (typ == 0)      { inv = temp[hd] / fmaxf(sqrtf(ss), 1e-12f); dst = Q; }
    else if (typ == 1) { inv = 1.f / fmaxf(sqrtf(ss), 1e-12f);      dst = K; }
    else               { inv = 1.f;                                  dst = V; }

    unsigned tmp[DP/2];
    #pragma unroll
    for (int i = CHD/2; i < DP/2; i++) tmp[i] = 0u;
    #pragma unroll
    for (int i = 0; i < CHD/2; i++) tmp[i] = cvt2(buf[2*i+1]*inv, buf[2*i]*inv);
    uint4* p4 = (uint4*)(dst + (size_t)idx*DP);
    p4[0] = make_uint4(tmp[0], tmp[1], tmp[2],  tmp[3]);
    p4[1] = make_uint4(tmp[4], tmp[5], tmp[6],  tmp[7]);
    p4[2] = make_uint4(tmp[8], tmp[9], tmp[10], tmp[11]);
    p4[3] = make_uint4(tmp[12],tmp[13],tmp[14], tmp[15]);
}

// ---------------- FFN depthwise 3x3 + gelu gate fused ----------------------
__global__ void dwconv_gate_kernel(const float* __restrict__ in, const float* __restrict__ w,
                                   const float* __restrict__ bias, float* __restrict__ out)
{
    int idx = blockIdx.x*blockDim.x + threadIdx.x;   // over BB*HID*NTOK
    if (idx >= BB*HID*NTOK) return;
    int p  = idx & (NTOK-1);
    int bj = idx >> 12;
    int j  = bj % HID;
    int b  = bj / HID;
    int x0 = p & 63, y0 = p >> 6;
    const float* ip1 = in + ((size_t)b*HID2 + j)*NTOK;
    const float* ip2 = in + ((size_t)b*HID2 + HID + j)*NTOK;
    const float* w1 = w + j*9;
    const float* w2 = w + (HID + j)*9;
    float a  = bias[j];
    float g2 = bias[HID + j];
    #pragma unroll
    for (int ky = 0; ky < 3; ky++) {
        int y = y0 + ky - 1;
        if ((unsigned)y < 64u) {
            #pragma unroll
            for (int kx = 0; kx < 3; kx++) {
                int xx = x0 + kx - 1;
                if ((unsigned)xx < 64u) {
                    a  += w1[ky*3 + kx] * ip1[y*64 + xx];
                    g2 += w2[ky*3 + kx] * ip2[y*64 + xx];
                }
            }
        }
    }
    float g = 0.5f*a*(1.f + erff(a*0.70710678118654752f));
    out[((size_t)b*HID + j)*NTOK + p] = g*g2;
}

// ---------------- bf16 mma.sync flash attention, split-KV, RED epilogue -----
#define KVSEG (NTOK/NSPL)   // 512

__global__ void __launch_bounds__(256)
attn_mma_kernel(const __nv_bfloat16* __restrict__ Qb,
                const __nv_bfloat16* __restrict__ Kb,
                const __nv_bfloat16* __restrict__ Vb,
                const float* __restrict__ temp,
                float* __restrict__ acc)
{
    __shared__ __align__(16) unsigned char smem_raw[2*16384];

    int tid  = threadIdx.x;
    int warp = tid >> 5, lane = tid & 31;
    int g    = lane >> 2;
    int t4   = lane & 3;
    int bh   = blockIdx.y;
    int q0   = blockIdx.x * 128;
    int spl  = blockIdx.z;
    int kv0  = spl * KVSEG;

    const float L2E = 1.4426950408889634f;
    float m  = fabsf(temp[bh & 1]);
    float nm = -m * L2E;

    unsigned qf[8];
    {
        const unsigned* q32 = (const unsigned*)(Qb + (size_t)(bh*NTOK + q0 + warp*16)*DP);
        #pragma unroll
        for (int kt = 0; kt < 2; kt++) {
            qf[kt*4+0] = q32[g*16       + kt*8 + t4];
            qf[kt*4+1] = q32[(g+8)*16   + kt*8 + t4];
            qf[kt*4+2] = q32[g*16       + kt*8 + 4 + t4];
            qf[kt*4+3] = q32[(g+8)*16   + kt*8 + 4 + t4];
        }
    }

    float o[12];
    #pragma unroll
    for (int i = 0; i < 12; i++) o[i] = 0.f;
    float l0 = 0.f, l1 = 0.f;

    const uint4* kg = (const uint4*)(Kb + (size_t)bh*NTOK*DP);
    const uint4* vg = (const uint4*)(Vb + (size_t)bh*NTOK*DP);
    int row = tid >> 2, chk = tid & 3;
    unsigned swz = row*128 + ((chk ^ (row & 7))*16);

    uint4 kreg = kg[(kv0 + row)*4 + chk];
    uint4 vreg = vg[(kv0 + row)*4 + chk];
    int it = 0;

    for (int kb = kv0; kb < kv0 + KVSEG; kb += 64) {
        unsigned char* bufK = smem_raw + it*16384;
        unsigned char* bufV = bufK + 8192;
        *(uint4*)(bufK + swz) = kreg;
        *(uint4*)(bufV + swz) = vreg;
        if (kb + 64 < kv0 + KVSEG) {
            kreg = kg[(kb + 64 + row)*4 + chk];
            vreg = vg[(kb + 64 + row)*4 + chk];
        }
        __syncthreads();

        unsigned pb[16];
        #pragma unroll
        for (int j = 0; j < 8; j++) {
            unsigned b0, b1, b2, b3;
            {
                int r = j*8 + (lane & 7);
                int c = lane >> 3;
                unsigned a = smem_u32(bufK + r*128 + ((c ^ (r & 7))*16));
                ldmx4(b0, b1, b2, b3, a);
            }
            float c0 = 0.f, c1 = 0.f, c2 = 0.f, c3 = 0.f;
            mma16816(c0, c1, c2, c3, qf[0], qf[1], qf[2], qf[3], b0, b1);
            mma16816(c0, c1, c2, c3, qf[4], qf[5], qf[6], qf[7], b2, b3);
            float p0 = ex2f(fmaf(c0, L2E, nm));
            float p1 = ex2f(fmaf(c1, L2E, nm));
            float p2 = ex2f(fmaf(c2, L2E, nm));
            float p3 = ex2f(fmaf(c3, L2E, nm));
            l0 += p0 + p1;
            l1 += p2 + p3;
            pb[(j>>1)*4 + (j&1)*2 + 0] = cvt2(p1, p0);
            pb[(j>>1)*4 + (j&1)*2 + 1] = cvt2(p3, p2);
        }

        #pragma unroll
        for (int t = 0; t < 4; t++) {
            #pragma unroll
            for (int p = 0; p < 2; p++) {
                unsigned b0, b1, b2, b3;
                {
                    int key = t*16 + ((lane >> 3) & 1)*8 + (lane & 7);
                    int c   = p*2 + (lane >> 4);
                    unsigned a = smem_u32(bufV + key*128 + ((c ^ (key & 7))*16));
                    ldmx4t(b0, b1, b2, b3, a);
                }
                int nn = p*2;
                mma16816(o[nn*4+0], o[nn*4+1], o[nn*4+2], o[nn*4+3],
                         pb[t*4], pb[t*4+1], pb[t*4+2], pb[t*4+3], b0, b1);
                if (nn + 1 < 3)
                    mma16816(o[nn*4+4], o[nn*4+5], o[nn*4+6], o[nn*4+7],
                             pb[t*4], pb[t*4+1], pb[t*4+2], pb[t*4+3], b2, b3);
            }
        }
        it ^= 1;
        // single sync per iteration (see R5): next store targets the other
        // buffer; the sync at the top of the next iteration orders reuse.
    }

    l0 += __shfl_xor_sync(0xffffffffu, l0, 1);
    l0 += __shfl_xor_sync(0xffffffffu, l0, 2);
    l1 += __shfl_xor_sync(0xffffffffu, l1, 1);
    l1 += __shfl_xor_sync(0xffffffffu, l1, 2);
    size_t r0 = (size_t)(bh*NTOK + q0 + warp*16 + g);
    float* a0 = acc + r0*ASTR;
    float* a1 = acc + (r0 + 8)*ASTR;
    #pragma unroll
    for (int nn = 0; nn < 3; nn++) {
        int cc = nn*8 + t4*2;
        atomicAdd(a0 + cc,     o[nn*4+0]);
        atomicAdd(a0 + cc + 1, o[nn*4+1]);
        atomicAdd(a1 + cc,     o[nn*4+2]);
        atomicAdd(a1 + cc + 1, o[nn*4+3]);
    }
    if (t4 == 0) { atomicAdd(a0 + 24, l0); atomicAdd(a1 + 24, l1); }
}

// -------- fused: normalize merged O + proj 1x1 + residual ------------------
// thread = pixel, OPT=16 output channels per thread, grid.y = 3.
__global__ void __launch_bounds__(256)
proj_merge_kernel(const float* __restrict__ acc, const float* __restrict__ x,
                  const float* __restrict__ pw, const float* __restrict__ pb,
                  float* __restrict__ out)
{
    const int OPT = 16;
    __shared__ float ws[CC0*OPT];      // [c][oo]
    const int o0 = blockIdx.y * OPT;
    for (int i = threadIdx.x; i < CC0*OPT; i += 256) {
        int oo = i % OPT, c = i / OPT;
        ws[i] = pw[(o0 + oo)*CC0 + c];
    }
    __syncthreads();

    int pix = blockIdx.x*256 + threadIdx.x;
    int b = pix >> 12, n = pix & (NTOK-1);

    float h0[25], h1[25];
    {
        const float4* r0 = (const float4*)(acc + ((size_t)(b*NHEADS + 0)*NTOK + n)*ASTR);
        const float4* r1 = (const float4*)(acc + ((size_t)(b*NHEADS + 1)*NTOK + n)*ASTR);
        #pragma unroll
        for (int i = 0; i < 6; i++) {
            float4 q = r0[i];
            h0[i*4+0]=q.x; h0[i*4+1]=q.y; h0[i*4+2]=q.z; h0[i*4+3]=q.w;
        }
        h0[24] = r0[6].x;
        #pragma unroll
        for (int i = 0; i < 6; i++) {
            float4 q = r1[i];
            h1[i*4+0]=q.x; h1[i*4+1]=q.y; h1[i*4+2]=q.z; h1[i*4+3]=q.w;
        }
        h1[24] = r1[6].x;
    }
    float inv0 = 1.f / h0[24];
    float inv1 = 1.f / h1[24];

    float accv[OPT];
    #pragma unroll
    for (int oo = 0; oo < OPT; oo++) accv[oo] = pb[o0 + oo];
    #pragma unroll
    for (int c = 0; c < CHD; c++) {
        float xc = h0[c]*inv0;
        #pragma unroll
        for (int oo = 0; oo < OPT; oo++)
            accv[oo] = fmaf(xc, ws[c*OPT + oo], accv[oo]);
    }
    #pragma unroll
    for (int c = 0; c < CHD; c++) {
        float xc = h1[c]*inv1;
        #pragma unroll
        for (int oo = 0; oo < OPT; oo++)
            accv[oo] = fmaf(xc, ws[(CHD + c)*OPT + oo], accv[oo]);
    }

    float* op = out + (size_t)(b*CC0 + o0)*NTOK + n;
    const float* rp = x + (size_t)(b*CC0 + o0)*NTOK + n;
    #pragma unroll
    for (int oo = 0; oo < OPT; oo++) op[oo*NTOK] = accv[oo] + rp[oo*NTOK];
}

// ---------------- launch ----------------------------------------------------
extern "C" void kernel_launch(void* const* d_in, const int* in_sizes, int n_in,
                              void* d_out, int out_size)
{
    const float* x    = (const float*)d_in[0];
    const float* n1w  = (const float*)d_in[1];
    const float* n1b  = (const float*)d_in[2];
    const float* qkvw = (const float*)d_in[3];
    const float* qkvb = (const float*)d_in[4];
    const float* qdww = (const float*)d_in[5];
    const float* qdwb = (const float*)d_in[6];
    const float* temp = (const float*)d_in[7];
    const float* pw   = (const float*)d_in[8];
    const float* pb   = (const float*)d_in[9];
    const float* n2w  = (const float*)d_in[10];
    const float* n2b  = (const float*)d_in[11];
    const float* fiw  = (const float*)d_in[12];
    const float* fib  = (const float*)d_in[13];
    const float* fdww = (const float*)d_in[14];
    const float* fdwb = (const float*)d_in[15];
    const float* fow  = (const float*)d_in[16];
    const float* fob  = (const float*)d_in[17];
    float* out = (float*)d_out;

    float *qkv1, *accp, *x1, *ff1, *ff3;
    __nv_bfloat16 *Qp, *Kp, *Vp;
    cudaGetSymbolAddress((void**)&qkv1, g_qkv1);
    cudaGetSymbolAddress((void**)&Qp,   g_qb);
    cudaGetSymbolAddress((void**)&Kp,   g_kb);
    cudaGetSymbolAddress((void**)&Vp,   g_vb);
    cudaGetSymbolAddress((void**)&accp, g_acc);
    cudaGetSymbolAddress((void**)&x1,   g_x1);
    cudaGetSymbolAddress((void**)&ff1,  g_ff1);
    cudaGetSymbolAddress((void**)&ff3,  g_ff3);

    // 1. LN1 + qkv 1x1 (also zeroes the attention accumulator)
    conv1x1_z<CC0, C3, 24, true><<<dim3(NPIX/256, C3/24), 256>>>(
        x, n1w, n1b, qkvw, qkvb, nullptr, qkv1, (float4*)accp, ACC_N4);
    // 2. fused depthwise 3x3 + split/l2norm/bf16 (type-parallel)
    dwconv_norm_kernel<<<dim3((BB*NHEADS*NTOK)/256, 3), 256>>>(
        qkv1, qdww, qdwb, temp, Qp, Kp, Vp);
    // 3. flash attention, split-KV, RED merge into g_acc
    dim3 ag(NTOK/128, BB*NHEADS, NSPL);
    attn_mma_kernel<<<ag, 256>>>(Qp, Kp, Vp, temp, accp);
    // 4. normalize + proj 1x1 + residual -> g_x1
    proj_merge_kernel<<<dim3(NPIX/256, 3), 256>>>(accp, x, pw, pb, x1);
    // 5. LN2 + fi 1x1 -> g_ff1 [b][192][pix]
    conv1x1_z<CC0, HID2, 24, true><<<dim3(NPIX/256, HID2/24), 256>>>(
        x1, n2w, n2b, fiw, fib, nullptr, ff1, nullptr, 0);
    // 6. FFN depthwise + gelu gate -> g_ff3 [b][96][pix]
    dwconv_gate_kernel<<<(BB*HID*NTOK + 255)/256, 256>>>(ff1, fdww, fdwb, ff3);
    // 7. fo 1x1 + residual -> out
    conv1x1_z<HID, CC0, 12, false><<<dim3(NPIX/256, CC0/12), 256>>>(
        ff3, nullptr, nullptr, fow, fob, x1, out, nullptr, 0);
}

// round 7
// speedup vs baseline: 1.2739x; 1.0202x over previous
#include <cuda_runtime.h>
#include <cuda_bf16.h>
#include <math.h>

// ---------------- problem constants ----------------
#define BB      2
#define CC0     48          // dim
#define NHEADS  2
#define CHD     24          // channels per head
#define DP      32          // padded head dim (bf16 tensors)
#define NTOK    4096        // 64*64
#define NPIX    (BB*NTOK)   // 8192
#define C3      144         // dim*3
#define HID     96
#define HID2    192
#define NSPL    8           // attention KV splits
#define ASTR    28          // accumulator record (floats, 16B aligned): 24 O + l

// ---------------- scratch (device globals; no allocation allowed) ----------
__device__ float g_qkv1[BB*C3*NTOK];
__device__ __nv_bfloat16 g_qb[BB*NHEADS*NTOK*DP];
__device__ __nv_bfloat16 g_kb[BB*NHEADS*NTOK*DP];
__device__ __nv_bfloat16 g_vb[BB*NHEADS*NTOK*DP];
__device__ float g_acc[BB*NHEADS*NTOK*ASTR];       // atomic O/l accumulator
__device__ float g_x1[BB*CC0*NTOK];
__device__ float g_ff1[BB*HID2*NTOK];
__device__ float g_ff3[BB*HID*NTOK];               // gated hidden

#define ACC_N4 ((BB*NHEADS*NTOK*ASTR)/4)           // float4 count = 114688

// ---------------- small asm helpers ----------------------------------------
__device__ __forceinline__ unsigned smem_u32(const void* p) {
    return (unsigned)__cvta_generic_to_shared(p);
}
__device__ __forceinline__ void ldmx4(unsigned& r0, unsigned& r1, unsigned& r2,
                                      unsigned& r3, unsigned a) {
    asm volatile("ldmatrix.sync.aligned.m8n8.x4.shared.b16 {%0,%1,%2,%3}, [%4];"
                 : "=r"(r0), "=r"(r1), "=r"(r2), "=r"(r3) : "r"(a));
}
__device__ __forceinline__ void ldmx4t(unsigned& r0, unsigned& r1, unsigned& r2,
                                       unsigned& r3, unsigned a) {
    asm volatile("ldmatrix.sync.aligned.m8n8.x4.trans.shared.b16 {%0,%1,%2,%3}, [%4];"
                 : "=r"(r0), "=r"(r1), "=r"(r2), "=r"(r3) : "r"(a));
}
__device__ __forceinline__ void mma16816(float& d0, float& d1, float& d2, float& d3,
                                         unsigned a0, unsigned a1, unsigned a2, unsigned a3,
                                         unsigned b0, unsigned b1) {
    asm volatile("mma.sync.aligned.m16n8k16.row.col.f32.bf16.bf16.f32 "
                 "{%0,%1,%2,%3},{%4,%5,%6,%7},{%8,%9},{%0,%1,%2,%3};"
                 : "+f"(d0), "+f"(d1), "+f"(d2), "+f"(d3)
                 : "r"(a0), "r"(a1), "r"(a2), "r"(a3), "r"(b0), "r"(b1));
}
__device__ __forceinline__ unsigned cvt2(float hi, float lo) {
    unsigned r;
    asm("cvt.rn.bf16x2.f32 %0, %1, %2;" : "=r"(r) : "f"(hi), "f"(lo));
    return r;
}
__device__ __forceinline__ float ex2f(float x) {
    float y; asm("ex2.approx.ftz.f32 %0, %1;" : "=f"(y) : "f"(x)); return y;
}

// ---------------- 1x1 conv (optionally LN in), z-sliced, 128-thread blocks --
// Also optionally zeroes a scratch buffer (piggyback, no extra launch).
template<int CIN, int COUT, int OPT, bool LN>
__global__ void __launch_bounds__(128)
conv1x1_z(const float* __restrict__ in,
          const float* __restrict__ lnw, const float* __restrict__ lnb,
          const float* __restrict__ w,   const float* __restrict__ bias,
          const float* __restrict__ res, float* __restrict__ out,
          float4* zbuf, int zn4)
{
    if (zbuf) {
        int nth  = gridDim.x*gridDim.y*128;
        int ztid = (blockIdx.y*gridDim.x + blockIdx.x)*128 + threadIdx.x;
        float4 z = make_float4(0.f, 0.f, 0.f, 0.f);
        for (int i = ztid; i < zn4; i += nth) zbuf[i] = z;
    }
    __shared__ float ws[CIN*OPT];      // [c][oo]
    const int o0 = blockIdx.y * OPT;
    for (int i = threadIdx.x; i < CIN*OPT; i += 128) {
        int oo = i % OPT, c = i / OPT;
        ws[i] = w[(o0 + oo)*CIN + c];
    }
    __syncthreads();

    int pix = blockIdx.x*128 + threadIdx.x;
    int b = pix >> 12, n = pix & (NTOK-1);
    const float* ip = in + (size_t)b*CIN*NTOK + n;

    float acc[OPT];
    #pragma unroll
    for (int oo = 0; oo < OPT; oo++) acc[oo] = bias[o0 + oo];

    if (LN) {
        float v[CIN];
        float s = 0.f, ss = 0.f;
        #pragma unroll
        for (int c = 0; c < CIN; c++) {
            float u = ip[c*NTOK];
            v[c] = u; s += u; ss += u*u;
        }
        float mu  = s * (1.f/CIN);
        float var = ss * (1.f/CIN) - mu*mu;
        float inv = rsqrtf(var + 1e-5f);
        #pragma unroll
        for (int c = 0; c < CIN; c++) {
            float xc = (v[c] - mu)*inv*__ldg(lnw + c) + __ldg(lnb + c);
            #pragma unroll
            for (int oo = 0; oo < OPT; oo++)
                acc[oo] = fmaf(xc, ws[c*OPT + oo], acc[oo]);
        }
    } else {
        #pragma unroll 4
        for (int c = 0; c < CIN; c++) {
            float xc = ip[c*NTOK];
            #pragma unroll
            for (int oo = 0; oo < OPT; oo++)
                acc[oo] = fmaf(xc, ws[c*OPT + oo], acc[oo]);
        }
    }

    float* op = out + (size_t)(b*COUT + o0)*NTOK + n;
    if (res) {
        const float* rp = res + (size_t)(b*COUT + o0)*NTOK + n;
        #pragma unroll
        for (int oo = 0; oo < OPT; oo++) op[oo*NTOK] = acc[oo] + rp[oo*NTOK];
    } else {
        #pragma unroll
        for (int oo = 0; oo < OPT; oo++) op[oo*NTOK] = acc[oo];
    }
}

// ------- fused: depthwise 3x3 + split/l2norm/temp + bf16 emit --------------
__global__ void __launch_bounds__(128)
dwconv_norm_kernel(const float* __restrict__ in, const float* __restrict__ w,
                   const float* __restrict__ bias, const float* __restrict__ temp,
                   __nv_bfloat16* __restrict__ Q, __nv_bfloat16* __restrict__ K,
                   __nv_bfloat16* __restrict__ V)
{
    int idx = blockIdx.x*128 + threadIdx.x;          // over BB*NHEADS*NTOK
    int typ = blockIdx.y;                            // 0=q, 1=k, 2=v
    int n  = idx & (NTOK-1);
    int bh = idx >> 12;
    int b = bh >> 1, hd = bh & 1;
    int x0 = n & 63, y0 = n >> 6;

    int off[9]; bool val[9];
    #pragma unroll
    for (int ky = 0; ky < 3; ky++) {
        int y = y0 + ky - 1;
        #pragma unroll
        for (int kx = 0; kx < 3; kx++) {
            int xx = x0 + kx - 1;
            int t = ky*3 + kx;
            val[t] = ((unsigned)y < 64u) && ((unsigned)xx < 64u);
            off[t] = y*64 + xx;
        }
    }

    float buf[CHD];
    float ss = 0.f;
    int ch0 = typ*CC0 + hd*CHD;
    #pragma unroll
    for (int c = 0; c < CHD; c++) {
        int ch = ch0 + c;
        const float* ip = in + ((size_t)b*C3 + ch)*NTOK;
        const float* wp = w + ch*9;
        float acc = bias[ch];
        #pragma unroll
        for (int tt = 0; tt < 9; tt++) if (val[tt]) acc += wp[tt]*ip[off[tt]];
        buf[c] = acc; ss += acc*acc;
    }
    float inv;
    __nv_bfloat16* dst;
    if (typ == 0)      { inv = temp[hd] / fmaxf(sqrtf(ss), 1e-12f); dst = Q; }
    else if (typ == 1) { inv = 1.f / fmaxf(sqrtf(ss), 1e-12f);      dst = K; }
    else               { inv = 1.f;                                  dst = V; }

    unsigned tmp[DP/2];
    #pragma unroll
    for (int i = CHD/2; i < DP/2; i++) tmp[i] = 0u;
    #pragma unroll
    for (int i = 0; i < CHD/2; i++) tmp[i] = cvt2(buf[2*i+1]*inv, buf[2*i]*inv);
    uint4* p4 = (uint4*)(dst + (size_t)idx*DP);
    p4[0] = make_uint4(tmp[0], tmp[1], tmp[2],  tmp[3]);
    p4[1] = make_uint4(tmp[4], tmp[5], tmp[6],  tmp[7]);
    p4[2] = make_uint4(tmp[8], tmp[9], tmp[10], tmp[11]);
    p4[3] = make_uint4(tmp[12],tmp[13],tmp[14], tmp[15]);
}

// ---------------- FFN depthwise 3x3 + gelu gate fused ----------------------
__global__ void dwconv_gate_kernel(const float* __restrict__ in, const float* __restrict__ w,
                                   const float* __restrict__ bias, float* __restrict__ out)
{
    int idx = blockIdx.x*blockDim.x + threadIdx.x;   // over BB*HID*NTOK
    if (idx >= BB*HID*NTOK) return;
    int p  = idx & (NTOK-1);
    int bj = idx >> 12;
    int j  = bj % HID;
    int b  = bj / HID;
    int x0 = p & 63, y0 = p >> 6;
    const float* ip1 = in + ((size_t)b*HID2 + j)*NTOK;
    const float* ip2 = in + ((size_t)b*HID2 + HID + j)*NTOK;
    const float* w1 = w + j*9;
    const float* w2 = w + (HID + j)*9;
    float a  = bias[j];
    float g2 = bias[HID + j];
    #pragma unroll
    for (int ky = 0; ky < 3; ky++) {
        int y = y0 + ky - 1;
        if ((unsigned)y < 64u) {
            #pragma unroll
            for (int kx = 0; kx < 3; kx++) {
                int xx = x0 + kx - 1;
                if ((unsigned)xx < 64u) {
                    a  += w1[ky*3 + kx] * ip1[y*64 + xx];
                    g2 += w2[ky*3 + kx] * ip2[y*64 + xx];
                }
            }
        }
    }
    float g = 0.5f*a*(1.f + erff(a*0.70710678118654752f));
    out[((size_t)b*HID + j)*NTOK + p] = g*g2;
}

// ---------------- bf16 mma.sync flash attention, split-KV, RED epilogue -----
#define KVSEG (NTOK/NSPL)   // 512

__global__ void __launch_bounds__(256)
attn_mma_kernel(const __nv_bfloat16* __restrict__ Qb,
                const __nv_bfloat16* __restrict__ Kb,
                const __nv_bfloat16* __restrict__ Vb,
                const float* __restrict__ temp,
                float* __restrict__ acc)
{
    __shared__ __align__(16) unsigned char smem_raw[2*16384];

    int tid  = threadIdx.x;
    int warp = tid >> 5, lane = tid & 31;
    int g    = lane >> 2;
    int t4   = lane & 3;
    int bh   = blockIdx.y;
    int q0   = blockIdx.x * 128;
    int spl  = blockIdx.z;
    int kv0  = spl * KVSEG;

    const float L2E = 1.4426950408889634f;
    float m  = fabsf(temp[bh & 1]);
    float nm = -m * L2E;

    unsigned qf[8];
    {
        const unsigned* q32 = (const unsigned*)(Qb + (size_t)(bh*NTOK + q0 + warp*16)*DP);
        #pragma unroll
        for (int kt = 0; kt < 2; kt++) {
            qf[kt*4+0] = q32[g*16       + kt*8 + t4];
            qf[kt*4+1] = q32[(g+8)*16   + kt*8 + t4];
            qf[kt*4+2] = q32[g*16       + kt*8 + 4 + t4];
            qf[kt*4+3] = q32[(g+8)*16   + kt*8 + 4 + t4];
        }
    }

    float o[12];
    #pragma unroll
    for (int i = 0; i < 12; i++) o[i] = 0.f;
    float l0 = 0.f, l1 = 0.f;

    const uint4* kg = (const uint4*)(Kb + (size_t)bh*NTOK*DP);
    const uint4* vg = (const uint4*)(Vb + (size_t)bh*NTOK*DP);
    int row = tid >> 2, chk = tid & 3;
    unsigned swz = row*128 + ((chk ^ (row & 7))*16);

    uint4 kreg = kg[(kv0 + row)*4 + chk];
    uint4 vreg = vg[(kv0 + row)*4 + chk];
    int it = 0;

    for (int kb = kv0; kb < kv0 + KVSEG; kb += 64) {
        unsigned char* bufK = smem_raw + it*16384;
        unsigned char* bufV = bufK + 8192;
        *(uint4*)(bufK + swz) = kreg;
        *(uint4*)(bufV + swz) = vreg;
        if (kb + 64 < kv0 + KVSEG) {
            kreg = kg[(kb + 64 + row)*4 + chk];
            vreg = vg[(kb + 64 + row)*4 + chk];
        }
        __syncthreads();

        unsigned pb[16];
        #pragma unroll
        for (int j = 0; j < 8; j++) {
            unsigned b0, b1, b2, b3;
            {
                int r = j*8 + (lane & 7);
                int c = lane >> 3;
                unsigned a = smem_u32(bufK + r*128 + ((c ^ (r & 7))*16));
                ldmx4(b0, b1, b2, b3, a);
            }
            float c0 = 0.f, c1 = 0.f, c2 = 0.f, c3 = 0.f;
            mma16816(c0, c1, c2, c3, qf[0], qf[1], qf[2], qf[3], b0, b1);
            mma16816(c0, c1, c2, c3, qf[4], qf[5], qf[6], qf[7], b2, b3);
            float p0 = ex2f(fmaf(c0, L2E, nm));
            float p1 = ex2f(fmaf(c1, L2E, nm));
            float p2 = ex2f(fmaf(c2, L2E, nm));
            float p3 = ex2f(fmaf(c3, L2E, nm));
            l0 += p0 + p1;
            l1 += p2 + p3;
            pb[(j>>1)*4 + (j&1)*2 + 0] = cvt2(p1, p0);
            pb[(j>>1)*4 + (j&1)*2 + 1] = cvt2(p3, p2);
        }

        #pragma unroll
        for (int t = 0; t < 4; t++) {
            #pragma unroll
            for (int p = 0; p < 2; p++) {
                unsigned b0, b1, b2, b3;
                {
                    int key = t*16 + ((lane >> 3) & 1)*8 + (lane & 7);
                    int c   = p*2 + (lane >> 4);
                    unsigned a = smem_u32(bufV + key*128 + ((c ^ (key & 7))*16));
                    ldmx4t(b0, b1, b2, b3, a);
                }
                int nn = p*2;
                mma16816(o[nn*4+0], o[nn*4+1], o[nn*4+2], o[nn*4+3],
                         pb[t*4], pb[t*4+1], pb[t*4+2], pb[t*4+3], b0, b1);
                if (nn + 1 < 3)
                    mma16816(o[nn*4+4], o[nn*4+5], o[nn*4+6], o[nn*4+7],
                             pb[t*4], pb[t*4+1], pb[t*4+2], pb[t*4+3], b2, b3);
            }
        }
        it ^= 1;
        // single sync per iteration (see R5): next store targets the other
        // buffer; the sync at the top of the next iteration orders reuse.
    }

    l0 += __shfl_xor_sync(0xffffffffu, l0, 1);
    l0 += __shfl_xor_sync(0xffffffffu, l0, 2);
    l1 += __shfl_xor_sync(0xffffffffu, l1, 1);
    l1 += __shfl_xor_sync(0xffffffffu, l1, 2);
    size_t r0 = (size_t)(bh*NTOK + q0 + warp*16 + g);
    float* a0 = acc + r0*ASTR;
    float* a1 = acc + (r0 + 8)*ASTR;
    #pragma unroll
    for (int nn = 0; nn < 3; nn++) {
        int cc = nn*8 + t4*2;
        atomicAdd(a0 + cc,     o[nn*4+0]);
        atomicAdd(a0 + cc + 1, o[nn*4+1]);
        atomicAdd(a1 + cc,     o[nn*4+2]);
        atomicAdd(a1 + cc + 1, o[nn*4+3]);
    }
    if (t4 == 0) { atomicAdd(a0 + 24, l0); atomicAdd(a1 + 24, l1); }
}

// -------- fused: normalize merged O + proj 1x1 + residual ------------------
// 128-thread blocks, OPT=8, grid (NPIX/128, 48/8) = (64, 6) = 384 CTAs.
__global__ void __launch_bounds__(128)
proj_merge_kernel(const float* __restrict__ acc, const float* __restrict__ x,
                  const float* __restrict__ pw, const float* __restrict__ pb,
                  float* __restrict__ out)
{
    const int OPT = 8;
    __shared__ float ws[CC0*OPT];      // [c][oo]
    const int o0 = blockIdx.y * OPT;
    for (int i = threadIdx.x; i < CC0*OPT; i += 128) {
        int oo = i % OPT, c = i / OPT;
        ws[i] = pw[(o0 + oo)*CC0 + c];
    }
    __syncthreads();

    int pix = blockIdx.x*128 + threadIdx.x;
    int b = pix >> 12, n = pix & (NTOK-1);

    float h0[25], h1[25];
    {
        const float4* r0 = (const float4*)(acc + ((size_t)(b*NHEADS + 0)*NTOK + n)*ASTR);
        const float4* r1 = (const float4*)(acc + ((size_t)(b*NHEADS + 1)*NTOK + n)*ASTR);
        #pragma unroll
        for (int i = 0; i < 6; i++) {
            float4 q = r0[i];
            h0[i*4+0]=q.x; h0[i*4+1]=q.y; h0[i*4+2]=q.z; h0[i*4+3]=q.w;
        }
        h0[24] = r0[6].x;
        #pragma unroll
        for (int i = 0; i < 6; i++) {
            float4 q = r1[i];
            h1[i*4+0]=q.x; h1[i*4+1]=q.y; h1[i*4+2]=q.z; h1[i*4+3]=q.w;
        }
        h1[24] = r1[6].x;
    }
    float inv0 = 1.f / h0[24];
    float inv1 = 1.f / h1[24];

    float accv[OPT];
    #pragma unroll
    for (int oo = 0; oo < OPT; oo++) accv[oo] = pb[o0 + oo];
    #pragma unroll
    for (int c = 0; c < CHD; c++) {
        float xc = h0[c]*inv0;
        #pragma unroll
        for (int oo = 0; oo < OPT; oo++)
            accv[oo] = fmaf(xc, ws[c*OPT + oo], accv[oo]);
    }
    #pragma unroll
    for (int c = 0; c < CHD; c++) {
        float xc = h1[c]*inv1;
        #pragma unroll
        for (int oo = 0; oo < OPT; oo++)
            accv[oo] = fmaf(xc, ws[(CHD + c)*OPT + oo], accv[oo]);
    }

    float* op = out + (size_t)(b*CC0 + o0)*NTOK + n;
    const float* rp = x + (size_t)(b*CC0 + o0)*NTOK + n;
    #pragma unroll
    for (int oo = 0; oo < OPT; oo++) op[oo*NTOK] = accv[oo] + rp[oo*NTOK];
}

// ---------------- launch ----------------------------------------------------
extern "C" void kernel_launch(void* const* d_in, const int* in_sizes, int n_in,
                              void* d_out, int out_size)
{
    const float* x    = (const float*)d_in[0];
    const float* n1w  = (const float*)d_in[1];
    const float* n1b  = (const float*)d_in[2];
    const float* qkvw = (const float*)d_in[3];
    const float* qkvb = (const float*)d_in[4];
    const float* qdww = (const float*)d_in[5];
    const float* qdwb = (const float*)d_in[6];
    const float* temp = (const float*)d_in[7];
    const float* pw   = (const float*)d_in[8];
    const float* pb   = (const float*)d_in[9];
    const float* n2w  = (const float*)d_in[10];
    const float* n2b  = (const float*)d_in[11];
    const float* fiw  = (const float*)d_in[12];
    const float* fib  = (const float*)d_in[13];
    const float* fdww = (const float*)d_in[14];
    const float* fdwb = (const float*)d_in[15];
    const float* fow  = (const float*)d_in[16];
    const float* fob  = (const float*)d_in[17];
    float* out = (float*)d_out;

    float *qkv1, *accp, *x1, *ff1, *ff3;
    __nv_bfloat16 *Qp, *Kp, *Vp;
    cudaGetSymbolAddress((void**)&qkv1, g_qkv1);
    cudaGetSymbolAddress((void**)&Qp,   g_qb);
    cudaGetSymbolAddress((void**)&Kp,   g_kb);
    cudaGetSymbolAddress((void**)&Vp,   g_vb);
    cudaGetSymbolAddress((void**)&accp, g_acc);
    cudaGetSymbolAddress((void**)&x1,   g_x1);
    cudaGetSymbolAddress((void**)&ff1,  g_ff1);
    cudaGetSymbolAddress((void**)&ff3,  g_ff3);

    // 1. LN1 + qkv 1x1 (also zeroes the attention accumulator)   384 CTAs
    conv1x1_z<CC0, C3, 24, true><<<dim3(NPIX/128, C3/24), 128>>>(
        x, n1w, n1b, qkvw, qkvb, nullptr, qkv1, (float4*)accp, ACC_N4);
    // 2. fused depthwise 3x3 + split/l2norm/bf16 (type-parallel) 384 CTAs
    dwconv_norm_kernel<<<dim3((BB*NHEADS*NTOK)/128, 3), 128>>>(
        qkv1, qdww, qdwb, temp, Qp, Kp, Vp);
    // 3. flash attention, split-KV, RED merge into g_acc        1024 CTAs
    dim3 ag(NTOK/128, BB*NHEADS, NSPL);
    attn_mma_kernel<<<ag, 256>>>(Qp, Kp, Vp, temp, accp);
    // 4. normalize + proj 1x1 + residual -> g_x1                 384 CTAs
    proj_merge_kernel<<<dim3(NPIX/128, CC0/8), 128>>>(accp, x, pw, pb, x1);
    // 5. LN2 + fi 1x1 -> g_ff1 [b][192][pix]                     512 CTAs
    conv1x1_z<CC0, HID2, 24, true><<<dim3(NPIX/128, HID2/24), 128>>>(
        x1, n2w, n2b, fiw, fib, nullptr, ff1, nullptr, 0);
    // 6. FFN depthwise + gelu gate -> g_ff3 [b][96][pix]        3072 CTAs
    dwconv_gate_kernel<<<(BB*HID*NTOK + 255)/256, 256>>>(ff1, fdww, fdwb, ff3);
    // 7. fo 1x1 + residual -> out                                256 CTAs
    conv1x1_z<HID, CC0, 12, false><<<dim3(NPIX/128, CC0/12), 128>>>(
        ff3, nullptr, nullptr, fow, fob, x1, out, nullptr, 0);
}

// round 8
// speedup vs baseline: 1.3675x; 1.0735x over previous
#include <cuda_runtime.h>
#include <cuda_bf16.h>
#include <math.h>

// ---------------- problem constants ----------------
#define BB      2
#define CC0     48          // dim
#define NHEADS  2
#define CHD     24          // channels per head
#define DP      32          // padded head dim (bf16 tensors)
#define NTOK    4096        // 64*64
#define NPIX    (BB*NTOK)   // 8192
#define C3      144         // dim*3
#define HID     96
#define HID2    192
#define NSPL    8           // attention KV splits
#define ASTR    28          // accumulator record (floats, 16B aligned): 24 O + l

// ---------------- scratch (device globals; no allocation allowed) ----------
__device__ float g_qkv1[BB*C3*NTOK];
__device__ __nv_bfloat16 g_qb[BB*NHEADS*NTOK*DP];
__device__ __nv_bfloat16 g_kb[BB*NHEADS*NTOK*DP];
__device__ __nv_bfloat16 g_vb[BB*NHEADS*NTOK*DP];
__device__ float g_acc[BB*NHEADS*NTOK*ASTR];       // atomic O/l accumulator
__device__ float g_x1[BB*CC0*NTOK];
__device__ float g_ff1[BB*HID2*NTOK];
__device__ float g_ff3[BB*HID*NTOK];               // gated hidden

#define ACC_N4 ((BB*NHEADS*NTOK*ASTR)/4)           // float4 count = 114688

// ---------------- small asm helpers ----------------------------------------
__device__ __forceinline__ unsigned smem_u32(const void* p) {
    return (unsigned)__cvta_generic_to_shared(p);
}
__device__ __forceinline__ void ldmx4(unsigned& r0, unsigned& r1, unsigned& r2,
                                      unsigned& r3, unsigned a) {
    asm volatile("ldmatrix.sync.aligned.m8n8.x4.shared.b16 {%0,%1,%2,%3}, [%4];"
                 : "=r"(r0), "=r"(r1), "=r"(r2), "=r"(r3) : "r"(a));
}
__device__ __forceinline__ void ldmx4t(unsigned& r0, unsigned& r1, unsigned& r2,
                                       unsigned& r3, unsigned a) {
    asm volatile("ldmatrix.sync.aligned.m8n8.x4.trans.shared.b16 {%0,%1,%2,%3}, [%4];"
                 : "=r"(r0), "=r"(r1), "=r"(r2), "=r"(r3) : "r"(a));
}
__device__ __forceinline__ void mma16816(float& d0, float& d1, float& d2, float& d3,
                                         unsigned a0, unsigned a1, unsigned a2, unsigned a3,
                                         unsigned b0, unsigned b1) {
    asm volatile("mma.sync.aligned.m16n8k16.row.col.f32.bf16.bf16.f32 "
                 "{%0,%1,%2,%3},{%4,%5,%6,%7},{%8,%9},{%0,%1,%2,%3};"
                 : "+f"(d0), "+f"(d1), "+f"(d2), "+f"(d3)
                 : "r"(a0), "r"(a1), "r"(a2), "r"(a3), "r"(b0), "r"(b1));
}
__device__ __forceinline__ unsigned cvt2(float hi, float lo) {
    unsigned r;
    asm("cvt.rn.bf16x2.f32 %0, %1, %2;" : "=r"(r) : "f"(hi), "f"(lo));
    return r;
}
__device__ __forceinline__ float ex2f(float x) {
    float y; asm("ex2.approx.ftz.f32 %0, %1;" : "=f"(y) : "f"(x)); return y;
}

// ---------------- 1x1 conv (optionally LN in), z-sliced, 128-thread blocks --
template<int CIN, int COUT, int OPT, bool LN>
__global__ void __launch_bounds__(128)
conv1x1_z(const float* __restrict__ in,
          const float* __restrict__ lnw, const float* __restrict__ lnb,
          const float* __restrict__ w,   const float* __restrict__ bias,
          const float* __restrict__ res, float* __restrict__ out,
          float4* zbuf, int zn4)
{
    if (zbuf) {
        int nth  = gridDim.x*gridDim.y*128;
        int ztid = (blockIdx.y*gridDim.x + blockIdx.x)*128 + threadIdx.x;
        float4 z = make_float4(0.f, 0.f, 0.f, 0.f);
        for (int i = ztid; i < zn4; i += nth) zbuf[i] = z;
    }
    __shared__ float ws[CIN*OPT];      // [c][oo]
    const int o0 = blockIdx.y * OPT;
    for (int i = threadIdx.x; i < CIN*OPT; i += 128) {
        int oo = i % OPT, c = i / OPT;
        ws[i] = w[(o0 + oo)*CIN + c];
    }
    __syncthreads();

    int pix = blockIdx.x*128 + threadIdx.x;
    int b = pix >> 12, n = pix & (NTOK-1);
    const float* ip = in + (size_t)b*CIN*NTOK + n;

    float acc[OPT];
    #pragma unroll
    for (int oo = 0; oo < OPT; oo++) acc[oo] = bias[o0 + oo];

    if (LN) {
        float v[CIN];
        float s = 0.f, ss = 0.f;
        #pragma unroll
        for (int c = 0; c < CIN; c++) {
            float u = ip[c*NTOK];
            v[c] = u; s += u; ss += u*u;
        }
        float mu  = s * (1.f/CIN);
        float var = ss * (1.f/CIN) - mu*mu;
        float inv = rsqrtf(var + 1e-5f);
        #pragma unroll
        for (int c = 0; c < CIN; c++) {
            float xc = (v[c] - mu)*inv*__ldg(lnw + c) + __ldg(lnb + c);
            #pragma unroll
            for (int oo = 0; oo < OPT; oo++)
                acc[oo] = fmaf(xc, ws[c*OPT + oo], acc[oo]);
        }
    } else {
        #pragma unroll 4
        for (int c = 0; c < CIN; c++) {
            float xc = ip[c*NTOK];
            #pragma unroll
            for (int oo = 0; oo < OPT; oo++)
                acc[oo] = fmaf(xc, ws[c*OPT + oo], acc[oo]);
        }
    }

    float* op = out + (size_t)(b*COUT + o0)*NTOK + n;
    if (res) {
        const float* rp = res + (size_t)(b*COUT + o0)*NTOK + n;
        #pragma unroll
        for (int oo = 0; oo < OPT; oo++) op[oo*NTOK] = acc[oo] + rp[oo*NTOK];
    } else {
        #pragma unroll
        for (int oo = 0; oo < OPT; oo++) op[oo*NTOK] = acc[oo];
    }
}

// ------- fused: depthwise 3x3 + split/l2norm/temp + bf16 emit --------------
// Q is additionally scaled by log2(e) (softmax done in base-2 domain).
// V gets a 1.0 in padding column 24: PV mma then produces the row-sum l.
__global__ void __launch_bounds__(128)
dwconv_norm_kernel(const float* __restrict__ in, const float* __restrict__ w,
                   const float* __restrict__ bias, const float* __restrict__ temp,
                   __nv_bfloat16* __restrict__ Q, __nv_bfloat16* __restrict__ K,
                   __nv_bfloat16* __restrict__ V)
{
    int idx = blockIdx.x*128 + threadIdx.x;          // over BB*NHEADS*NTOK
    int typ = blockIdx.y;                            // 0=q, 1=k, 2=v
    int n  = idx & (NTOK-1);
    int bh = idx >> 12;
    int b = bh >> 1, hd = bh & 1;
    int x0 = n & 63, y0 = n >> 6;

    int off[9]; bool val[9];
    #pragma unroll
    for (int ky = 0; ky < 3; ky++) {
        int y = y0 + ky - 1;
        #pragma unroll
        for (int kx = 0; kx < 3; kx++) {
            int xx = x0 + kx - 1;
            int t = ky*3 + kx;
            val[t] = ((unsigned)y < 64u) && ((unsigned)xx < 64u);
            off[t] = y*64 + xx;
        }
    }

    float buf[CHD];
    float ss = 0.f;
    int ch0 = typ*CC0 + hd*CHD;
    #pragma unroll
    for (int c = 0; c < CHD; c++) {
        int ch = ch0 + c;
        const float* ip = in + ((size_t)b*C3 + ch)*NTOK;
        const float* wp = w + ch*9;
        float acc = bias[ch];
        #pragma unroll
        for (int tt = 0; tt < 9; tt++) if (val[tt]) acc += wp[tt]*ip[off[tt]];
        buf[c] = acc; ss += acc*acc;
    }
    const float L2E = 1.4426950408889634f;
    float inv;
    __nv_bfloat16* dst;
    if (typ == 0)      { inv = temp[hd]*L2E / fmaxf(sqrtf(ss), 1e-12f); dst = Q; }
    else if (typ == 1) { inv = 1.f / fmaxf(sqrtf(ss), 1e-12f);          dst = K; }
    else               { inv = 1.f;                                      dst = V; }

    unsigned tmp[DP/2];
    #pragma unroll
    for (int i = CHD/2; i < DP/2; i++) tmp[i] = 0u;
    #pragma unroll
    for (int i = 0; i < CHD/2; i++) tmp[i] = cvt2(buf[2*i+1]*inv, buf[2*i]*inv);
    if (typ == 2) tmp[12] = cvt2(0.f, 1.f);   // V col 24 = 1.0 -> l via mma
    uint4* p4 = (uint4*)(dst + (size_t)idx*DP);
    p4[0] = make_uint4(tmp[0], tmp[1], tmp[2],  tmp[3]);
    p4[1] = make_uint4(tmp[4], tmp[5], tmp[6],  tmp[7]);
    p4[2] = make_uint4(tmp[8], tmp[9], tmp[10], tmp[11]);
    p4[3] = make_uint4(tmp[12],tmp[13],tmp[14], tmp[15]);
}

// ---------------- FFN depthwise 3x3 + gelu gate fused ----------------------
__global__ void dwconv_gate_kernel(const float* __restrict__ in, const float* __restrict__ w,
                                   const float* __restrict__ bias, float* __restrict__ out)
{
    int idx = blockIdx.x*blockDim.x + threadIdx.x;   // over BB*HID*NTOK
    if (idx >= BB*HID*NTOK) return;
    int p  = idx & (NTOK-1);
    int bj = idx >> 12;
    int j  = bj % HID;
    int b  = bj / HID;
    int x0 = p & 63, y0 = p >> 6;
    const float* ip1 = in + ((size_t)b*HID2 + j)*NTOK;
    const float* ip2 = in + ((size_t)b*HID2 + HID + j)*NTOK;
    const float* w1 = w + j*9;
    const float* w2 = w + (HID + j)*9;
    float a  = bias[j];
    float g2 = bias[HID + j];
    #pragma unroll
    for (int ky = 0; ky < 3; ky++) {
        int y = y0 + ky - 1;
        if ((unsigned)y < 64u) {
            #pragma unroll
            for (int kx = 0; kx < 3; kx++) {
                int xx = x0 + kx - 1;
                if ((unsigned)xx < 64u) {
                    a  += w1[ky*3 + kx] * ip1[y*64 + xx];
                    g2 += w2[ky*3 + kx] * ip2[y*64 + xx];
                }
            }
        }
    }
    float g = 0.5f*a*(1.f + erff(a*0.70710678118654752f));
    out[((size_t)b*HID + j)*NTOK + p] = g*g2;
}

// ---------------- bf16 mma.sync flash attention, split-KV, RED epilogue -----
// Q pre-scaled by L2E*t; S accumulators init at -|t|*L2E so p = ex2(c).
// V col 24 = 1 so PV tile 3 computes row-sum l.
#define KVSEG (NTOK/NSPL)   // 512

__global__ void __launch_bounds__(256)
attn_mma_kernel(const __nv_bfloat16* __restrict__ Qb,
                const __nv_bfloat16* __restrict__ Kb,
                const __nv_bfloat16* __restrict__ Vb,
                const float* __restrict__ temp,
                float* __restrict__ acc)
{
    __shared__ __align__(16) unsigned char smem_raw[2*16384];

    int tid  = threadIdx.x;
    int warp = tid >> 5, lane = tid & 31;
    int g    = lane >> 2;
    int t4   = lane & 3;
    int bh   = blockIdx.y;
    int q0   = blockIdx.x * 128;
    int spl  = blockIdx.z;
    int kv0  = spl * KVSEG;

    const float L2E = 1.4426950408889634f;
    float nm = -fabsf(temp[bh & 1]) * L2E;

    unsigned qf[8];
    {
        const unsigned* q32 = (const unsigned*)(Qb + (size_t)(bh*NTOK + q0 + warp*16)*DP);
        #pragma unroll
        for (int kt = 0; kt < 2; kt++) {
            qf[kt*4+0] = q32[g*16       + kt*8 + t4];
            qf[kt*4+1] = q32[(g+8)*16   + kt*8 + t4];
            qf[kt*4+2] = q32[g*16       + kt*8 + 4 + t4];
            qf[kt*4+3] = q32[(g+8)*16   + kt*8 + 4 + t4];
        }
    }

    float o[16];
    #pragma unroll
    for (int i = 0; i < 16; i++) o[i] = 0.f;

    const uint4* kg = (const uint4*)(Kb + (size_t)bh*NTOK*DP);
    const uint4* vg = (const uint4*)(Vb + (size_t)bh*NTOK*DP);
    int row = tid >> 2, chk = tid & 3;
    unsigned swz = row*128 + ((chk ^ (row & 7))*16);

    uint4 kreg = kg[(kv0 + row)*4 + chk];
    uint4 vreg = vg[(kv0 + row)*4 + chk];
    int it = 0;

    for (int kb = kv0; kb < kv0 + KVSEG; kb += 64) {
        unsigned char* bufK = smem_raw + it*16384;
        unsigned char* bufV = bufK + 8192;
        *(uint4*)(bufK + swz) = kreg;
        *(uint4*)(bufV + swz) = vreg;
        if (kb + 64 < kv0 + KVSEG) {
            kreg = kg[(kb + 64 + row)*4 + chk];
            vreg = vg[(kb + 64 + row)*4 + chk];
        }
        __syncthreads();

        unsigned pb[16];
        #pragma unroll
        for (int j = 0; j < 8; j++) {
            unsigned b0, b1, b2, b3;
            {
                int r = j*8 + (lane & 7);
                int c = lane >> 3;
                unsigned a = smem_u32(bufK + r*128 + ((c ^ (r & 7))*16));
                ldmx4(b0, b1, b2, b3, a);
            }
            float c0 = nm, c1 = nm, c2 = nm, c3 = nm;
            mma16816(c0, c1, c2, c3, qf[0], qf[1], qf[2], qf[3], b0, b1);
            mma16816(c0, c1, c2, c3, qf[4], qf[5], qf[6], qf[7], b2, b3);
            float p0 = ex2f(c0);
            float p1 = ex2f(c1);
            float p2 = ex2f(c2);
            float p3 = ex2f(c3);
            pb[(j>>1)*4 + (j&1)*2 + 0] = cvt2(p1, p0);
            pb[(j>>1)*4 + (j&1)*2 + 1] = cvt2(p3, p2);
        }

        #pragma unroll
        for (int t = 0; t < 4; t++) {
            #pragma unroll
            for (int p = 0; p < 2; p++) {
                unsigned b0, b1, b2, b3;
                {
                    int key = t*16 + ((lane >> 3) & 1)*8 + (lane & 7);
                    int c   = p*2 + (lane >> 4);
                    unsigned a = smem_u32(bufV + key*128 + ((c ^ (key & 7))*16));
                    ldmx4t(b0, b1, b2, b3, a);
                }
                int nn = p*2;
                mma16816(o[nn*4+0], o[nn*4+1], o[nn*4+2], o[nn*4+3],
                         pb[t*4], pb[t*4+1], pb[t*4+2], pb[t*4+3], b0, b1);
                mma16816(o[nn*4+4], o[nn*4+5], o[nn*4+6], o[nn*4+7],
                         pb[t*4], pb[t*4+1], pb[t*4+2], pb[t*4+3], b2, b3);
            }
        }
        it ^= 1;
        // single sync per iteration (see R5): next store targets the other
        // buffer; the sync at the top of the next iteration orders reuse.
    }

    size_t r0 = (size_t)(bh*NTOK + q0 + warp*16 + g);
    float* a0 = acc + r0*ASTR;
    float* a1 = acc + (r0 + 8)*ASTR;
    #pragma unroll
    for (int nn = 0; nn < 3; nn++) {
        int cc = nn*8 + t4*2;
        atomicAdd(a0 + cc,     o[nn*4+0]);
        atomicAdd(a0 + cc + 1, o[nn*4+1]);
        atomicAdd(a1 + cc,     o[nn*4+2]);
        atomicAdd(a1 + cc + 1, o[nn*4+3]);
    }
    if (t4 == 0) { atomicAdd(a0 + 24, o[12]); atomicAdd(a1 + 24, o[14]); }
}

// -------- fused: normalize merged O + proj 1x1 + residual ------------------
// 64-thread blocks, OPT=8, grid (NPIX/64, 48/8) = (128, 6) = 768 CTAs.
// Heads processed sequentially to keep register count low.
__global__ void __launch_bounds__(64)
proj_merge_kernel(const float* __restrict__ acc, const float* __restrict__ x,
                  const float* __restrict__ pw, const float* __restrict__ pb,
                  float* __restrict__ out)
{
    const int OPT = 8;
    __shared__ float ws[CC0*OPT];      // [c][oo]
    const int o0 = blockIdx.y * OPT;
    for (int i = threadIdx.x; i < CC0*OPT; i += 64) {
        int oo = i % OPT, c = i / OPT;
        ws[i] = pw[(o0 + oo)*CC0 + c];
    }
    __syncthreads();

    int pix = blockIdx.x*64 + threadIdx.x;
    int b = pix >> 12, n = pix & (NTOK-1);

    float accv[OPT];
    #pragma unroll
    for (int oo = 0; oo < OPT; oo++) accv[oo] = pb[o0 + oo];

    #pragma unroll
    for (int hd = 0; hd < NHEADS; hd++) {
        float h[25];
        const float4* r = (const float4*)(acc + ((size_t)(b*NHEADS + hd)*NTOK + n)*ASTR);
        #pragma unroll
        for (int i = 0; i < 6; i++) {
            float4 q = r[i];
            h[i*4+0]=q.x; h[i*4+1]=q.y; h[i*4+2]=q.z; h[i*4+3]=q.w;
        }
        h[24] = r[6].x;
        float inv = 1.f / h[24];
        #pragma unroll
        for (int c = 0; c < CHD; c++) {
            float xc = h[c]*inv;
            #pragma unroll
            for (int oo = 0; oo < OPT; oo++)
                accv[oo] = fmaf(xc, ws[(hd*CHD + c)*OPT + oo], accv[oo]);
        }
    }

    float* op = out + (size_t)(b*CC0 + o0)*NTOK + n;
    const float* rp = x + (size_t)(b*CC0 + o0)*NTOK + n;
    #pragma unroll
    for (int oo = 0; oo < OPT; oo++) op[oo*NTOK] = accv[oo] + rp[oo*NTOK];
}

// ---------------- launch ----------------------------------------------------
extern "C" void kernel_launch(void* const* d_in, const int* in_sizes, int n_in,
                              void* d_out, int out_size)
{
    const float* x    = (const float*)d_in[0];
    const float* n1w  = (const float*)d_in[1];
    const float* n1b  = (const float*)d_in[2];
    const float* qkvw = (const float*)d_in[3];
    const float* qkvb = (const float*)d_in[4];
    const float* qdww = (const float*)d_in[5];
    const float* qdwb = (const float*)d_in[6];
    const float* temp = (const float*)d_in[7];
    const float* pw   = (const float*)d_in[8];
    const float* pb   = (const float*)d_in[9];
    const float* n2w  = (const float*)d_in[10];
    const float* n2b  = (const float*)d_in[11];
    const float* fiw  = (const float*)d_in[12];
    const float* fib  = (const float*)d_in[13];
    const float* fdww = (const float*)d_in[14];
    const float* fdwb = (const float*)d_in[15];
    const float* fow  = (const float*)d_in[16];
    const float* fob  = (const float*)d_in[17];
    float* out = (float*)d_out;

    float *qkv1, *accp, *x1, *ff1, *ff3;
    __nv_bfloat16 *Qp, *Kp, *Vp;
    cudaGetSymbolAddress((void**)&qkv1, g_qkv1);
    cudaGetSymbolAddress((void**)&Qp,   g_qb);
    cudaGetSymbolAddress((void**)&Kp,   g_kb);
    cudaGetSymbolAddress((void**)&Vp,   g_vb);
    cudaGetSymbolAddress((void**)&accp, g_acc);
    cudaGetSymbolAddress((void**)&x1,   g_x1);
    cudaGetSymbolAddress((void**)&ff1,  g_ff1);
    cudaGetSymbolAddress((void**)&ff3,  g_ff3);

    // 1. LN1 + qkv 1x1 (also zeroes the attention accumulator)   384 CTAs
    conv1x1_z<CC0, C3, 24, true><<<dim3(NPIX/128, C3/24), 128>>>(
        x, n1w, n1b, qkvw, qkvb, nullptr, qkv1, (float4*)accp, ACC_N4);
    // 2. fused depthwise 3x3 + split/l2norm/bf16 (type-parallel) 384 CTAs
    dwconv_norm_kernel<<<dim3((BB*NHEADS*NTOK)/128, 3), 128>>>(
        qkv1, qdww, qdwb, temp, Qp, Kp, Vp);
    // 3. flash attention, split-KV, RED merge into g_acc        1024 CTAs
    dim3 ag(NTOK/128, BB*NHEADS, NSPL);
    attn_mma_kernel<<<ag, 256>>>(Qp, Kp, Vp, temp, accp);
    // 4. normalize + proj 1x1 + residual -> g_x1                 768 CTAs
    proj_merge_kernel<<<dim3(NPIX/64, CC0/8), 64>>>(accp, x, pw, pb, x1);
    // 5. LN2 + fi 1x1 -> g_ff1 [b][192][pix]                     512 CTAs
    conv1x1_z<CC0, HID2, 24, true><<<dim3(NPIX/128, HID2/24), 128>>>(
        x1, n2w, n2b, fiw, fib, nullptr, ff1, nullptr, 0);
    // 6. FFN depthwise + gelu gate -> g_ff3 [b][96][pix]        3072 CTAs
    dwconv_gate_kernel<<<(BB*HID*NTOK + 255)/256, 256>>>(ff1, fdww, fdwb, ff3);
    // 7. fo 1x1 + residual -> out                                384 CTAs
    conv1x1_z<HID, CC0, 8, false><<<dim3(NPIX/128, CC0/8), 128>>>(
        ff3, nullptr, nullptr, fow, fob, x1, out, nullptr, 0);
}

// round 9
// speedup vs baseline: 1.3686x; 1.0008x over previous
#include <cuda_runtime.h>
#include <cuda_bf16.h>
#include <math.h>

// ---------------- problem constants ----------------
#define BB      2
#define CC0     48          // dim
#define NHEADS  2
#define CHD     24          // channels per head
#define DP      32          // padded head dim (bf16 tensors)
#define NTOK    4096        // 64*64
#define NPIX    (BB*NTOK)   // 8192
#define C3      144         // dim*3
#define HID     96
#define HID2    192
#define NSPL    8           // attention KV splits
#define ASTR    28          // accumulator record (floats, 16B aligned): 24 O + l

// ---------------- scratch (device globals; no allocation allowed) ----------
__device__ float g_qkv1[BB*C3*NTOK];
__device__ __nv_bfloat16 g_qb[BB*NHEADS*NTOK*DP];
__device__ __nv_bfloat16 g_kb[BB*NHEADS*NTOK*DP];
__device__ __nv_bfloat16 g_vb[BB*NHEADS*NTOK*DP];
__device__ float g_acc[BB*NHEADS*NTOK*ASTR];       // atomic O/l accumulator
__device__ float g_x1[BB*CC0*NTOK];
__device__ float g_ff1[BB*HID2*NTOK];
__device__ float g_ff3[BB*HID*NTOK];               // gated hidden

#define ACC_N4 ((BB*NHEADS*NTOK*ASTR)/4)           // float4 count = 114688

// ---------------- small asm helpers ----------------------------------------
__device__ __forceinline__ unsigned smem_u32(const void* p) {
    return (unsigned)__cvta_generic_to_shared(p);
}
__device__ __forceinline__ void ldmx4(unsigned& r0, unsigned& r1, unsigned& r2,
                                      unsigned& r3, unsigned a) {
    asm volatile("ldmatrix.sync.aligned.m8n8.x4.shared.b16 {%0,%1,%2,%3}, [%4];"
                 : "=r"(r0), "=r"(r1), "=r"(r2), "=r"(r3) : "r"(a));
}
__device__ __forceinline__ void ldmx4t(unsigned& r0, unsigned& r1, unsigned& r2,
                                       unsigned& r3, unsigned a) {
    asm volatile("ldmatrix.sync.aligned.m8n8.x4.trans.shared.b16 {%0,%1,%2,%3}, [%4];"
                 : "=r"(r0), "=r"(r1), "=r"(r2), "=r"(r3) : "r"(a));
}
__device__ __forceinline__ void mma16816(float& d0, float& d1, float& d2, float& d3,
                                         unsigned a0, unsigned a1, unsigned a2, unsigned a3,
                                         unsigned b0, unsigned b1) {
    asm volatile("mma.sync.aligned.m16n8k16.row.col.f32.bf16.bf16.f32 "
                 "{%0,%1,%2,%3},{%4,%5,%6,%7},{%8,%9},{%0,%1,%2,%3};"
                 : "+f"(d0), "+f"(d1), "+f"(d2), "+f"(d3)
                 : "r"(a0), "r"(a1), "r"(a2), "r"(a3), "r"(b0), "r"(b1));
}
__device__ __forceinline__ unsigned cvt2(float hi, float lo) {
    unsigned r;
    asm("cvt.rn.bf16x2.f32 %0, %1, %2;" : "=r"(r) : "f"(hi), "f"(lo));
    return r;
}
__device__ __forceinline__ float ex2f(float x) {
    float y; asm("ex2.approx.ftz.f32 %0, %1;" : "=f"(y) : "f"(x)); return y;
}

// ---------------- 1x1 conv (optionally LN in), z-sliced, 128-thread blocks --
template<int CIN, int COUT, int OPT, bool LN>
__global__ void __launch_bounds__(128)
conv1x1_z(const float* __restrict__ in,
          const float* __restrict__ lnw, const float* __restrict__ lnb,
          const float* __restrict__ w,   const float* __restrict__ bias,
          const float* __restrict__ res, float* __restrict__ out,
          float4* zbuf, int zn4)
{
    if (zbuf) {
        int nth  = gridDim.x*gridDim.y*128;
        int ztid = (blockIdx.y*gridDim.x + blockIdx.x)*128 + threadIdx.x;
        float4 z = make_float4(0.f, 0.f, 0.f, 0.f);
        for (int i = ztid; i < zn4; i += nth) zbuf[i] = z;
    }
    __shared__ float ws[CIN*OPT];      // [c][oo]
    const int o0 = blockIdx.y * OPT;
    for (int i = threadIdx.x; i < CIN*OPT; i += 128) {
        int oo = i % OPT, c = i / OPT;
        ws[i] = w[(o0 + oo)*CIN + c];
    }
    __syncthreads();

    int pix = blockIdx.x*128 + threadIdx.x;
    int b = pix >> 12, n = pix & (NTOK-1);
    const float* ip = in + (size_t)b*CIN*NTOK + n;

    float acc[OPT];
    #pragma unroll
    for (int oo = 0; oo < OPT; oo++) acc[oo] = bias[o0 + oo];

    if (LN) {
        float v[CIN];
        float s = 0.f, ss = 0.f;
        #pragma unroll
        for (int c = 0; c < CIN; c++) {
            float u = ip[c*NTOK];
            v[c] = u; s += u; ss += u*u;
        }
        float mu  = s * (1.f/CIN);
        float var = ss * (1.f/CIN) - mu*mu;
        float inv = rsqrtf(var + 1e-5f);
        #pragma unroll
        for (int c = 0; c < CIN; c++) {
            float xc = (v[c] - mu)*inv*__ldg(lnw + c) + __ldg(lnb + c);
            #pragma unroll
            for (int oo = 0; oo < OPT; oo++)
                acc[oo] = fmaf(xc, ws[c*OPT + oo], acc[oo]);
        }
    } else {
        #pragma unroll 4
        for (int c = 0; c < CIN; c++) {
            float xc = ip[c*NTOK];
            #pragma unroll
            for (int oo = 0; oo < OPT; oo++)
                acc[oo] = fmaf(xc, ws[c*OPT + oo], acc[oo]);
        }
    }

    float* op = out + (size_t)(b*COUT + o0)*NTOK + n;
    if (res) {
        const float* rp = res + (size_t)(b*COUT + o0)*NTOK + n;
        #pragma unroll
        for (int oo = 0; oo < OPT; oo++) op[oo*NTOK] = acc[oo] + rp[oo*NTOK];
    } else {
        #pragma unroll
        for (int oo = 0; oo < OPT; oo++) op[oo*NTOK] = acc[oo];
    }
}

// ------- fused: depthwise 3x3 + split/l2norm/temp + bf16 emit --------------
// 2 threads per (bh, token): each computes 12 of the 24 head channels;
// sum-of-squares combined via one shuffle. Q scaled by L2E*t; V col24 = 1.
__global__ void __launch_bounds__(128)
dwconv_norm_kernel(const float* __restrict__ in, const float* __restrict__ w,
                   const float* __restrict__ bias, const float* __restrict__ temp,
                   __nv_bfloat16* __restrict__ Q, __nv_bfloat16* __restrict__ K,
                   __nv_bfloat16* __restrict__ V)
{
    int gt   = blockIdx.x*128 + threadIdx.x;         // over BB*NHEADS*NTOK*2
    int half = gt & 1;
    int idx  = gt >> 1;                              // (bh, token)
    int typ  = blockIdx.y;                           // 0=q, 1=k, 2=v
    int n  = idx & (NTOK-1);
    int bh = idx >> 12;
    int b = bh >> 1, hd = bh & 1;
    int x0 = n & 63, y0 = n >> 6;

    int off[9]; bool val[9];
    #pragma unroll
    for (int ky = 0; ky < 3; ky++) {
        int y = y0 + ky - 1;
        #pragma unroll
        for (int kx = 0; kx < 3; kx++) {
            int xx = x0 + kx - 1;
            int t = ky*3 + kx;
            val[t] = ((unsigned)y < 64u) && ((unsigned)xx < 64u);
            off[t] = y*64 + xx;
        }
    }

    float buf[12];
    float ss = 0.f;
    int ch0 = typ*CC0 + hd*CHD + half*12;
    #pragma unroll
    for (int c = 0; c < 12; c++) {
        int ch = ch0 + c;
        const float* ip = in + ((size_t)b*C3 + ch)*NTOK;
        const float* wp = w + ch*9;
        float acc = bias[ch];
        #pragma unroll
        for (int tt = 0; tt < 9; tt++) if (val[tt]) acc += wp[tt]*ip[off[tt]];
        buf[c] = acc; ss += acc*acc;
    }
    ss += __shfl_xor_sync(0xffffffffu, ss, 1);       // pair-combine

    const float L2E = 1.4426950408889634f;
    float inv;
    __nv_bfloat16* dst;
    if (typ == 0)      { inv = temp[hd]*L2E / fmaxf(sqrtf(ss), 1e-12f); dst = Q; }
    else if (typ == 1) { inv = 1.f / fmaxf(sqrtf(ss), 1e-12f);          dst = K; }
    else               { inv = 1.f;                                      dst = V; }

    unsigned tmp[6];
    #pragma unroll
    for (int i = 0; i < 6; i++) tmp[i] = cvt2(buf[2*i+1]*inv, buf[2*i]*inv);
    char* base = (char*)(dst + (size_t)idx*DP) + half*24;
    ((uint2*)base)[0]        = make_uint2(tmp[0], tmp[1]);
    ((uint2*)(base + 8))[0]  = make_uint2(tmp[2], tmp[3]);
    ((uint2*)(base + 16))[0] = make_uint2(tmp[4], tmp[5]);
    if (half) {   // padding cols 24..31 (V gets 1.0 in col 24 -> l via mma)
        unsigned pad0 = (typ == 2) ? cvt2(0.f, 1.f) : 0u;
        *(uint4*)((char*)(dst + (size_t)idx*DP) + 48) = make_uint4(pad0, 0u, 0u, 0u);
    }
}

// ---------------- FFN depthwise 3x3 + gelu gate fused ----------------------
__global__ void dwconv_gate_kernel(const float* __restrict__ in, const float* __restrict__ w,
                                   const float* __restrict__ bias, float* __restrict__ out)
{
    int idx = blockIdx.x*blockDim.x + threadIdx.x;   // over BB*HID*NTOK
    if (idx >= BB*HID*NTOK) return;
    int p  = idx & (NTOK-1);
    int bj = idx >> 12;
    int j  = bj % HID;
    int b  = bj / HID;
    int x0 = p & 63, y0 = p >> 6;
    const float* ip1 = in + ((size_t)b*HID2 + j)*NTOK;
    const float* ip2 = in + ((size_t)b*HID2 + HID + j)*NTOK;
    const float* w1 = w + j*9;
    const float* w2 = w + (HID + j)*9;
    float a  = bias[j];
    float g2 = bias[HID + j];
    #pragma unroll
    for (int ky = 0; ky < 3; ky++) {
        int y = y0 + ky - 1;
        if ((unsigned)y < 64u) {
            #pragma unroll
            for (int kx = 0; kx < 3; kx++) {
                int xx = x0 + kx - 1;
                if ((unsigned)xx < 64u) {
                    a  += w1[ky*3 + kx] * ip1[y*64 + xx];
                    g2 += w2[ky*3 + kx] * ip2[y*64 + xx];
                }
            }
        }
    }
    float g = 0.5f*a*(1.f + erff(a*0.70710678118654752f));
    out[((size_t)b*HID + j)*NTOK + p] = g*g2;
}

// ---------------- bf16 mma.sync flash attention, split-KV, RED epilogue -----
#define KVSEG (NTOK/NSPL)   // 512

__global__ void __launch_bounds__(256)
attn_mma_kernel(const __nv_bfloat16* __restrict__ Qb,
                const __nv_bfloat16* __restrict__ Kb,
                const __nv_bfloat16* __restrict__ Vb,
                const float* __restrict__ temp,
                float* __restrict__ acc)
{
    __shared__ __align__(16) unsigned char smem_raw[2*16384];

    int tid  = threadIdx.x;
    int warp = tid >> 5, lane = tid & 31;
    int g    = lane >> 2;
    int t4   = lane & 3;
    int bh   = blockIdx.y;
    int q0   = blockIdx.x * 128;
    int spl  = blockIdx.z;
    int kv0  = spl * KVSEG;

    const float L2E = 1.4426950408889634f;
    float nm = -fabsf(temp[bh & 1]) * L2E;

    unsigned qf[8];
    {
        const unsigned* q32 = (const unsigned*)(Qb + (size_t)(bh*NTOK + q0 + warp*16)*DP);
        #pragma unroll
        for (int kt = 0; kt < 2; kt++) {
            qf[kt*4+0] = q32[g*16       + kt*8 + t4];
            qf[kt*4+1] = q32[(g+8)*16   + kt*8 + t4];
            qf[kt*4+2] = q32[g*16       + kt*8 + 4 + t4];
            qf[kt*4+3] = q32[(g+8)*16   + kt*8 + 4 + t4];
        }
    }

    float o[16];
    #pragma unroll
    for (int i = 0; i < 16; i++) o[i] = 0.f;

    const uint4* kg = (const uint4*)(Kb + (size_t)bh*NTOK*DP);
    const uint4* vg = (const uint4*)(Vb + (size_t)bh*NTOK*DP);
    int row = tid >> 2, chk = tid & 3;
    unsigned swz = row*128 + ((chk ^ (row & 7))*16);

    uint4 kreg = kg[(kv0 + row)*4 + chk];
    uint4 vreg = vg[(kv0 + row)*4 + chk];
    int it = 0;

    for (int kb = kv0; kb < kv0 + KVSEG; kb += 64) {
        unsigned char* bufK = smem_raw + it*16384;
        unsigned char* bufV = bufK + 8192;
        *(uint4*)(bufK + swz) = kreg;
        *(uint4*)(bufV + swz) = vreg;
        if (kb + 64 < kv0 + KVSEG) {
            kreg = kg[(kb + 64 + row)*4 + chk];
            vreg = vg[(kb + 64 + row)*4 + chk];
        }
        __syncthreads();

        unsigned pb[16];
        #pragma unroll
        for (int j = 0; j < 8; j++) {
            unsigned b0, b1, b2, b3;
            {
                int r = j*8 + (lane & 7);
                int c = lane >> 3;
                unsigned a = smem_u32(bufK + r*128 + ((c ^ (r & 7))*16));
                ldmx4(b0, b1, b2, b3, a);
            }
            float c0 = nm, c1 = nm, c2 = nm, c3 = nm;
            mma16816(c0, c1, c2, c3, qf[0], qf[1], qf[2], qf[3], b0, b1);
            mma16816(c0, c1, c2, c3, qf[4], qf[5], qf[6], qf[7], b2, b3);
            float p0 = ex2f(c0);
            float p1 = ex2f(c1);
            float p2 = ex2f(c2);
            float p3 = ex2f(c3);
            pb[(j>>1)*4 + (j&1)*2 + 0] = cvt2(p1, p0);
            pb[(j>>1)*4 + (j&1)*2 + 1] = cvt2(p3, p2);
        }

        #pragma unroll
        for (int t = 0; t < 4; t++) {
            #pragma unroll
            for (int p = 0; p < 2; p++) {
                unsigned b0, b1, b2, b3;
                {
                    int key = t*16 + ((lane >> 3) & 1)*8 + (lane & 7);
                    int c   = p*2 + (lane >> 4);
                    unsigned a = smem_u32(bufV + key*128 + ((c ^ (key & 7))*16));
                    ldmx4t(b0, b1, b2, b3, a);
                }
                int nn = p*2;
                mma16816(o[nn*4+0], o[nn*4+1], o[nn*4+2], o[nn*4+3],
                         pb[t*4], pb[t*4+1], pb[t*4+2], pb[t*4+3], b0, b1);
                mma16816(o[nn*4+4], o[nn*4+5], o[nn*4+6], o[nn*4+7],
                         pb[t*4], pb[t*4+1], pb[t*4+2], pb[t*4+3], b2, b3);
            }
        }
        it ^= 1;
    }

    size_t r0 = (size_t)(bh*NTOK + q0 + warp*16 + g);
    float* a0 = acc + r0*ASTR;
    float* a1 = acc + (r0 + 8)*ASTR;
    #pragma unroll
    for (int nn = 0; nn < 3; nn++) {
        int cc = nn*8 + t4*2;
        atomicAdd(a0 + cc,     o[nn*4+0]);
        atomicAdd(a0 + cc + 1, o[nn*4+1]);
        atomicAdd(a1 + cc,     o[nn*4+2]);
        atomicAdd(a1 + cc + 1, o[nn*4+3]);
    }
    if (t4 == 0) { atomicAdd(a0 + 24, o[12]); atomicAdd(a1 + 24, o[14]); }
}

// -------- fused: normalize merged O + proj 1x1 + residual ------------------
// 128-thread blocks, OPT=4, grid (NPIX/128, 48/4) = (64, 12) = 768 CTAs.
__global__ void __launch_bounds__(128)
proj_merge_kernel(const float* __restrict__ acc, const float* __restrict__ x,
                  const float* __restrict__ pw, const float* __restrict__ pb,
                  float* __restrict__ out)
{
    const int OPT = 4;
    __shared__ float ws[CC0*OPT];      // [c][oo]
    const int o0 = blockIdx.y * OPT;
    for (int i = threadIdx.x; i < CC0*OPT; i += 128) {
        int oo = i % OPT, c = i / OPT;
        ws[i] = pw[(o0 + oo)*CC0 + c];
    }
    __syncthreads();

    int pix = blockIdx.x*128 + threadIdx.x;
    int b = pix >> 12, n = pix & (NTOK-1);

    float accv[OPT];
    #pragma unroll
    for (int oo = 0; oo < OPT; oo++) accv[oo] = pb[o0 + oo];

    #pragma unroll
    for (int hd = 0; hd < NHEADS; hd++) {
        float h[25];
        const float4* r = (const float4*)(acc + ((size_t)(b*NHEADS + hd)*NTOK + n)*ASTR);
        #pragma unroll
        for (int i = 0; i < 6; i++) {
            float4 q = r[i];
            h[i*4+0]=q.x; h[i*4+1]=q.y; h[i*4+2]=q.z; h[i*4+3]=q.w;
        }
        h[24] = r[6].x;
        float inv = 1.f / h[24];
        #pragma unroll
        for (int c = 0; c < CHD; c++) {
            float xc = h[c]*inv;
            #pragma unroll
            for (int oo = 0; oo < OPT; oo++)
                accv[oo] = fmaf(xc, ws[(hd*CHD + c)*OPT + oo], accv[oo]);
        }
    }

    float* op = out + (size_t)(b*CC0 + o0)*NTOK + n;
    const float* rp = x + (size_t)(b*CC0 + o0)*NTOK + n;
    #pragma unroll
    for (int oo = 0; oo < OPT; oo++) op[oo*NTOK] = accv[oo] + rp[oo*NTOK];
}

// ---------------- launch ----------------------------------------------------
extern "C" void kernel_launch(void* const* d_in, const int* in_sizes, int n_in,
                              void* d_out, int out_size)
{
    const float* x    = (const float*)d_in[0];
    const float* n1w  = (const float*)d_in[1];
    const float* n1b  = (const float*)d_in[2];
    const float* qkvw = (const float*)d_in[3];
    const float* qkvb = (const float*)d_in[4];
    const float* qdww = (const float*)d_in[5];
    const float* qdwb = (const float*)d_in[6];
    const float* temp = (const float*)d_in[7];
    const float* pw   = (const float*)d_in[8];
    const float* pb   = (const float*)d_in[9];
    const float* n2w  = (const float*)d_in[10];
    const float* n2b  = (const float*)d_in[11];
    const float* fiw  = (const float*)d_in[12];
    const float* fib  = (const float*)d_in[13];
    const float* fdww = (const float*)d_in[14];
    const float* fdwb = (const float*)d_in[15];
    const float* fow  = (const float*)d_in[16];
    const float* fob  = (const float*)d_in[17];
    float* out = (float*)d_out;

    float *qkv1, *accp, *x1, *ff1, *ff3;
    __nv_bfloat16 *Qp, *Kp, *Vp;
    cudaGetSymbolAddress((void**)&qkv1, g_qkv1);
    cudaGetSymbolAddress((void**)&Qp,   g_qb);
    cudaGetSymbolAddress((void**)&Kp,   g_kb);
    cudaGetSymbolAddress((void**)&Vp,   g_vb);
    cudaGetSymbolAddress((void**)&accp, g_acc);
    cudaGetSymbolAddress((void**)&x1,   g_x1);
    cudaGetSymbolAddress((void**)&ff1,  g_ff1);
    cudaGetSymbolAddress((void**)&ff3,  g_ff3);

    // 1. LN1 + qkv 1x1 (also zeroes attn accumulator)      (64,18)=1152 CTAs
    conv1x1_z<CC0, C3, 8, true><<<dim3(NPIX/128, C3/8), 128>>>(
        x, n1w, n1b, qkvw, qkvb, nullptr, qkv1, (float4*)accp, ACC_N4);
    // 2. fused depthwise 3x3 + split/l2norm/bf16           (256,3)=768 CTAs
    dwconv_norm_kernel<<<dim3((BB*NHEADS*NTOK*2)/128, 3), 128>>>(
        qkv1, qdww, qdwb, temp, Qp, Kp, Vp);
    // 3. flash attention, split-KV, RED merge into g_acc        1024 CTAs
    dim3 ag(NTOK/128, BB*NHEADS, NSPL);
    attn_mma_kernel<<<ag, 256>>>(Qp, Kp, Vp, temp, accp);
    // 4. normalize + proj 1x1 + residual -> g_x1           (64,12)=768 CTAs
    proj_merge_kernel<<<dim3(NPIX/128, CC0/4), 128>>>(accp, x, pw, pb, x1);
    // 5. LN2 + fi 1x1 -> g_ff1                             (64,16)=1024 CTAs
    conv1x1_z<CC0, HID2, 12, true><<<dim3(NPIX/128, HID2/12), 128>>>(
        x1, n2w, n2b, fiw, fib, nullptr, ff1, nullptr, 0);
    // 6. FFN depthwise + gelu gate -> g_ff3                     3072 CTAs
    dwconv_gate_kernel<<<(BB*HID*NTOK + 255)/256, 256>>>(ff1, fdww, fdwb, ff3);
    // 7. fo 1x1 + residual -> out                          (64,8)=512 CTAs
    conv1x1_z<HID, CC0, 6, false><<<dim3(NPIX/128, CC0/6), 128>>>(
        ff3, nullptr, nullptr, fow, fob, x1, out, nullptr, 0);
}